// round 9
// baseline (speedup 1.0000x reference)
#include <cuda_runtime.h>
#include <cuda_bf16.h>
#include <stdint.h>

// Problem constants
#define Bn  2
#define Sn  2048
#define Dn  1024
#define Hn  16
#define DHn 64
#define BHn (Bn*Hn)
#define CSC 0.18033688f   // 0.125 * log2(e)

// ---------------------------------------------------------------------------
// Scratch (static __device__) — everything bf16 hi/lo planes except g_T
// ---------------------------------------------------------------------------
__device__ uint16_t g_Qh[(size_t)Bn*Sn*Dn], g_Ql[(size_t)Bn*Sn*Dn];
__device__ uint16_t g_Kh[(size_t)Bn*Sn*Dn], g_Kl[(size_t)Bn*Sn*Dn];
__device__ uint16_t g_Vh[(size_t)Bn*Sn*Dn], g_Vl[(size_t)Bn*Sn*Dn];
__device__ uint16_t g_KRh[(size_t)Sn*Dn],   g_KRl[(size_t)Sn*Dn];
__device__ uint16_t g_xh[(size_t)Bn*Sn*Dn], g_xl[(size_t)Bn*Sn*Dn];
__device__ uint16_t g_ph[(size_t)Sn*Dn],    g_pl[(size_t)Sn*Dn];
__device__ uint16_t g_Wth[(size_t)5*Dn*Dn], g_Wtl[(size_t)5*Dn*Dn]; // q,k,v,kr,o transposed [n][k]
__device__ uint16_t g_AOh[(size_t)Bn*Sn*Dn], g_AOl[(size_t)Bn*Sn*Dn];
__device__ float    g_T [(size_t)BHn*Sn*Sn];

// ---------------------------------------------------------------------------
// Helpers
// ---------------------------------------------------------------------------
__device__ __forceinline__ uint32_t smem_u32(const void* p) {
    uint32_t a;
    asm("{ .reg .u64 t; cvta.to.shared.u64 t, %1; cvt.u32.u64 %0, t; }"
        : "=r"(a) : "l"(p));
    return a;
}
__device__ __forceinline__ void ldm4(uint32_t addr, uint32_t* r) {
    asm volatile("ldmatrix.sync.aligned.m8n8.x4.shared.b16 {%0,%1,%2,%3}, [%4];"
        : "=r"(r[0]), "=r"(r[1]), "=r"(r[2]), "=r"(r[3]) : "r"(addr));
}
__device__ __forceinline__ void ldm4t(uint32_t addr, uint32_t* r) {
    asm volatile("ldmatrix.sync.aligned.m8n8.x4.trans.shared.b16 {%0,%1,%2,%3}, [%4];"
        : "=r"(r[0]), "=r"(r[1]), "=r"(r[2]), "=r"(r[3]) : "r"(addr));
}
__device__ __forceinline__ void mma16816(float* c, const uint32_t* a, const uint32_t* b) {
    asm volatile(
        "mma.sync.aligned.m16n8k16.row.col.f32.bf16.bf16.f32 "
        "{%0,%1,%2,%3}, {%4,%5,%6,%7}, {%8,%9}, {%0,%1,%2,%3};"
        : "+f"(c[0]), "+f"(c[1]), "+f"(c[2]), "+f"(c[3])
        : "r"(a[0]), "r"(a[1]), "r"(a[2]), "r"(a[3]), "r"(b[0]), "r"(b[1]));
}
__device__ __forceinline__ float ex2f(float x) {
    float y; asm("ex2.approx.ftz.f32 %0, %1;" : "=f"(y) : "f"(x)); return y;
}
__device__ __forceinline__ void cvt2(float x0, float x1, uint32_t& hi, uint32_t& lo) {
    __nv_bfloat16 h0 = __float2bfloat16(x0);
    __nv_bfloat16 h1 = __float2bfloat16(x1);
    __nv_bfloat16 l0 = __float2bfloat16(x0 - __bfloat162float(h0));
    __nv_bfloat16 l1 = __float2bfloat16(x1 - __bfloat162float(h1));
    hi = (uint32_t)__bfloat16_as_ushort(h0) | ((uint32_t)__bfloat16_as_ushort(h1) << 16);
    lo = (uint32_t)__bfloat16_as_ushort(l0) | ((uint32_t)__bfloat16_as_ushort(l1) << 16);
}
__device__ __forceinline__ float2 unpack_bf2(uint32_t w) {
    return make_float2(
        __bfloat162float(__ushort_as_bfloat16((unsigned short)(w & 0xFFFFu))),
        __bfloat162float(__ushort_as_bfloat16((unsigned short)(w >> 16))));
}
__device__ __forceinline__ void cpa16(uint32_t dst, const void* src) {
    asm volatile("cp.async.cg.shared.global [%0], [%1], 16;" :: "r"(dst), "l"(src));
}
#define CPA_COMMIT()  asm volatile("cp.async.commit_group;" ::: "memory")
#define CPA_WAIT(N)   asm volatile("cp.async.wait_group %0;" :: "n"(N) : "memory")

// ---------------------------------------------------------------------------
// One-time plane conversion kernels
// ---------------------------------------------------------------------------
__global__ __launch_bounds__(256)
void conv_elem(const float* __restrict__ src, uint16_t* __restrict__ dh,
               uint16_t* __restrict__ dl, int n4)
{
    int i = blockIdx.x * 256 + threadIdx.x;
    if (i >= n4) return;
    float4 v = ((const float4*)src)[i];
    uint32_t h0, l0, h1, l1;
    cvt2(v.x, v.y, h0, l0);  cvt2(v.z, v.w, h1, l1);
    ((uint32_t*)dh)[i*2]   = h0;  ((uint32_t*)dh)[i*2+1] = h1;
    ((uint32_t*)dl)[i*2]   = l0;  ((uint32_t*)dl)[i*2+1] = l1;
}

__global__ __launch_bounds__(256)
void conv_wt(const float* __restrict__ Wq, const float* __restrict__ Wk,
             const float* __restrict__ Wv, const float* __restrict__ Wkr,
             const float* __restrict__ Wo)
{
    __shared__ float tile[32][33];
    const int z = blockIdx.z;
    const float* W = (z == 0) ? Wq : (z == 1) ? Wk : (z == 2) ? Wv
                   : (z == 3) ? Wkr : Wo;
    uint16_t* oh = g_Wth + (size_t)z * Dn * Dn;
    uint16_t* ol = g_Wtl + (size_t)z * Dn * Dn;
    const int k0 = blockIdx.y << 5, n0 = blockIdx.x << 5;
    const int tr = threadIdx.x >> 5, tc = threadIdx.x & 31;
#pragma unroll
    for (int i = 0; i < 4; i++)
        tile[tr + i*8][tc] = W[(size_t)(k0 + tr + i*8) * Dn + n0 + tc];
    __syncthreads();
#pragma unroll
    for (int i = 0; i < 4; i++) {
        int n = tr + i*8;
        float v = tile[tc][n];
        __nv_bfloat16 hb = __float2bfloat16(v);
        __nv_bfloat16 lb = __float2bfloat16(v - __bfloat162float(hb));
        oh[(size_t)(n0 + n) * Dn + k0 + tc] = __bfloat16_as_ushort(hb);
        ol[(size_t)(n0 + n) * Dn + k0 + tc] = __bfloat16_as_ushort(lb);
    }
}

// ---------------------------------------------------------------------------
// Plane GEMM: C[M,1024] = A @ B^T (+bias). 256 thr, 8 warps (32x64 tiles),
// 5-stage cp.async pipeline (4 chunks in flight), K-chunk 32.
// ---------------------------------------------------------------------------
#define SPITCH 40
#define GOA_HI 0
#define GOA_LO 5120
#define GOB_HI 10240
#define GOB_LO 15360
#define GSTAGE_SZ 20480                  // b16 per stage (40960 B)
#define NSTG 5
#define GEMM_SMEM (NSTG*GSTAGE_SZ*2)     // 204800 bytes

__device__ __forceinline__
void gemm_issue(uint32_t stage_b, const uint16_t* Ah, const uint16_t* Al,
                const uint16_t* Bh, const uint16_t* Bl,
                int k0, int row0, int col0, int t)
{
    const int p = t >> 7, r = t & 127;
    const uint16_t* As = (p ? Al : Ah) + (size_t)(row0 + r) * Dn + k0;
    const uint16_t* Bs = (p ? Bl : Bh) + (size_t)(col0 + r) * Dn + k0;
    uint32_t ad = stage_b + (p ? GOA_LO : GOA_HI)*2 + r*80;
    uint32_t bd = stage_b + (p ? GOB_LO : GOB_HI)*2 + r*80;
#pragma unroll
    for (int i = 0; i < 4; i++) {
        cpa16(ad + i*16, As + i*8);
        cpa16(bd + i*16, Bs + i*8);
    }
}

template<bool PLANES>
__device__ __forceinline__
void gemm_body(const uint16_t* __restrict__ Ah, const uint16_t* __restrict__ Al,
               const uint16_t* __restrict__ Bh, const uint16_t* __restrict__ Bl,
               const float* __restrict__ bias, float* __restrict__ C,
               uint16_t* __restrict__ Chi, uint16_t* __restrict__ Clo,
               int row0, int col0, uint16_t* sm)
{
    const int t = threadIdx.x, lane = t & 31, wid = t >> 5;
    const int m0w = (wid & 3) << 5, n0w = (wid >> 2) << 6;
    const int q = lane >> 3, r8 = lane & 7;
    const uint32_t sb = smem_u32(sm);
    const int NC = Dn >> 5;   // 32 chunks

    // prelude: 4 chunks in flight
#pragma unroll
    for (int s = 0; s < 4; s++) {
        gemm_issue(sb + s*GSTAGE_SZ*2, Ah, Al, Bh, Bl, s*32, row0, col0, t);
        CPA_COMMIT();
    }

    float acc[2][8][4];
#pragma unroll
    for (int mt = 0; mt < 2; mt++)
#pragma unroll
        for (int nt = 0; nt < 8; nt++)
#pragma unroll
            for (int c = 0; c < 4; c++) acc[mt][nt][c] = 0.f;

    for (int c = 0; c < NC; c++) {
        CPA_WAIT(3);
        __syncthreads();
        // stage (c+4)%5 == (c-1)%5 was consumed last iteration -> free
        if (c + 4 < NC)
            gemm_issue(sb + ((c + 4) % NSTG) * GSTAGE_SZ * 2,
                       Ah, Al, Bh, Bl, (c + 4) * 32, row0, col0, t);
        CPA_COMMIT();

        const uint32_t cb = sb + (c % NSTG) * GSTAGE_SZ * 2;
#pragma unroll
        for (int ks = 0; ks < 2; ks++) {
            uint32_t ahi[2][4], alo[2][4];
#pragma unroll
            for (int mt = 0; mt < 2; mt++) {
                int row = m0w + mt*16 + r8 + (q & 1)*8;
                int col = ks*16 + (q >> 1)*8;
                uint32_t off = (uint32_t)(row*SPITCH + col) * 2;
                ldm4(cb + GOA_HI*2 + off, ahi[mt]);
                ldm4(cb + GOA_LO*2 + off, alo[mt]);
            }
            uint32_t bhi[8][2], blo[8][2];
#pragma unroll
            for (int bt = 0; bt < 4; bt++) {
                int row = n0w + bt*16 + r8 + (q >> 1)*8;
                int col = ks*16 + (q & 1)*8;
                uint32_t off = (uint32_t)(row*SPITCH + col) * 2;
                uint32_t tmp[4];
                ldm4(cb + GOB_HI*2 + off, tmp);
                bhi[bt*2][0]=tmp[0]; bhi[bt*2][1]=tmp[1];
                bhi[bt*2+1][0]=tmp[2]; bhi[bt*2+1][1]=tmp[3];
                ldm4(cb + GOB_LO*2 + off, tmp);
                blo[bt*2][0]=tmp[0]; blo[bt*2][1]=tmp[1];
                blo[bt*2+1][0]=tmp[2]; blo[bt*2+1][1]=tmp[3];
            }
#pragma unroll
            for (int mt = 0; mt < 2; mt++)
#pragma unroll
                for (int nt = 0; nt < 8; nt++) {
                    mma16816(acc[mt][nt], ahi[mt], bhi[nt]);
                    mma16816(acc[mt][nt], ahi[mt], blo[nt]);
                    mma16816(acc[mt][nt], alo[mt], bhi[nt]);
                }
        }
    }

#pragma unroll
    for (int mt = 0; mt < 2; mt++) {
        int m = row0 + m0w + mt*16 + lane/4;
#pragma unroll
        for (int nt = 0; nt < 8; nt++) {
            int n = col0 + n0w + nt*8 + (lane & 3)*2;
            float2 b2 = *(const float2*)(bias + n);
            float v0 = acc[mt][nt][0] + b2.x, v1 = acc[mt][nt][1] + b2.y;
            float v2 = acc[mt][nt][2] + b2.x, v3 = acc[mt][nt][3] + b2.y;
            if (PLANES) {
                uint32_t h, l;
                cvt2(v0, v1, h, l);
                *(uint32_t*)&Chi[(size_t)m*Dn + n] = h;
                *(uint32_t*)&Clo[(size_t)m*Dn + n] = l;
                cvt2(v2, v3, h, l);
                *(uint32_t*)&Chi[(size_t)(m+8)*Dn + n] = h;
                *(uint32_t*)&Clo[(size_t)(m+8)*Dn + n] = l;
            } else {
                float* Cp0 = C + (size_t)m * Dn + n;
                float* Cp1 = Cp0 + (size_t)8 * Dn;
                Cp0[0] = v0;  Cp0[1] = v1;
                Cp1[0] = v2;  Cp1[1] = v3;
            }
        }
    }
}

__global__ __launch_bounds__(256, 1)
void proj_fused(const float* __restrict__ bq, const float* __restrict__ bk,
                const float* __restrict__ bv, const float* __restrict__ bkr)
{
    extern __shared__ uint16_t gsm[];
    const int z = blockIdx.z;
    const int row0 = blockIdx.y << 7, col0 = blockIdx.x << 7;
    if (z == 3 && row0 >= Sn) return;
    const uint16_t *Ah, *Al; const float* bias; uint16_t *Chi, *Clo;
    if (z < 3) { Ah = g_xh; Al = g_xl; } else { Ah = g_ph; Al = g_pl; }
    if      (z == 0) { bias = bq;  Chi = g_Qh;  Clo = g_Ql;  }
    else if (z == 1) { bias = bk;  Chi = g_Kh;  Clo = g_Kl;  }
    else if (z == 2) { bias = bv;  Chi = g_Vh;  Clo = g_Vl;  }
    else             { bias = bkr; Chi = g_KRh; Clo = g_KRl; }
    const uint16_t* Bh = g_Wth + (size_t)z * Dn * Dn;
    const uint16_t* Bl = g_Wtl + (size_t)z * Dn * Dn;
    gemm_body<true>(Ah, Al, Bh, Bl, bias, nullptr, Chi, Clo, row0, col0, gsm);
}

__global__ __launch_bounds__(256, 1)
void mma_gemm_wo(const float* __restrict__ bias, float* __restrict__ C)
{
    extern __shared__ uint16_t gsm[];
    gemm_body<false>(g_AOh, g_AOl,
                     g_Wth + (size_t)4 * Dn * Dn, g_Wtl + (size_t)4 * Dn * Dn,
                     bias, C, nullptr, nullptr,
                     blockIdx.y << 7, blockIdx.x << 7, gsm);
}

// ---------------------------------------------------------------------------
// NT GEMM from planes:  T[bh] = Q_bh [S,64] @ KR_h^T  (unchanged from R8)
// ---------------------------------------------------------------------------
#define TP 72
#define TAH 0
#define TAL (128*TP)
#define TBH (2*128*TP)
#define TBL (3*128*TP)
#define TSMEM (4*128*TP*2)

__global__ __launch_bounds__(256, 1)
void mma_gemm_t()
{
    extern __shared__ uint16_t tsm[];
    const int t = threadIdx.x, lane = t & 31, wid = t >> 5;
    const int bh = blockIdx.z, b = bh >> 4, h = bh & 15;
    const int row0 = blockIdx.y << 7, col0 = blockIdx.x << 7;
    const int m0w = (wid & 3) << 5, n0w = (wid >> 2) << 6;
    const int q = lane >> 3, r8 = lane & 7;

    float* C = g_T + (size_t)bh * Sn * Sn;

    {
        const int r = t >> 1, c = (t & 1) << 5;
        const size_t soA = ((size_t)b*Sn + row0 + r) * Dn + h*DHn + c;
        const size_t soB = ((size_t)col0 + r) * Dn + h*DHn + c;
        const uint32_t sb = smem_u32(tsm);
        uint32_t da = sb + (TAH + r*TP + c)*2;
        uint32_t dl = sb + (TAL + r*TP + c)*2;
        uint32_t db = sb + (TBH + r*TP + c)*2;
        uint32_t dbl = sb + (TBL + r*TP + c)*2;
#pragma unroll
        for (int i = 0; i < 4; i++) {
            cpa16(da + i*16,  g_Qh  + soA + i*8);
            cpa16(dl + i*16,  g_Ql  + soA + i*8);
            cpa16(db + i*16,  g_KRh + soB + i*8);
            cpa16(dbl + i*16, g_KRl + soB + i*8);
        }
        CPA_COMMIT();
        CPA_WAIT(0);
    }
    __syncthreads();

    float acc[2][8][4];
#pragma unroll
    for (int mt = 0; mt < 2; mt++)
#pragma unroll
        for (int nt = 0; nt < 8; nt++)
#pragma unroll
            for (int c = 0; c < 4; c++) acc[mt][nt][c] = 0.f;

    const uint32_t cb = smem_u32(tsm);
#pragma unroll
    for (int ks = 0; ks < 4; ks++) {
        uint32_t ahi[2][4], alo[2][4];
#pragma unroll
        for (int mt = 0; mt < 2; mt++) {
            int row = m0w + mt*16 + r8 + (q & 1)*8;
            int col = ks*16 + (q >> 1)*8;
            uint32_t off = (uint32_t)(row*TP + col) * 2;
            ldm4(cb + TAH*2 + off, ahi[mt]);
            ldm4(cb + TAL*2 + off, alo[mt]);
        }
        uint32_t bhi[8][2], blo[8][2];
#pragma unroll
        for (int bt = 0; bt < 4; bt++) {
            int row = n0w + bt*16 + r8 + (q >> 1)*8;
            int col = ks*16 + (q & 1)*8;
            uint32_t off = (uint32_t)(row*TP + col) * 2;
            uint32_t tmp[4];
            ldm4(cb + TBH*2 + off, tmp);
            bhi[bt*2][0]=tmp[0]; bhi[bt*2][1]=tmp[1];
            bhi[bt*2+1][0]=tmp[2]; bhi[bt*2+1][1]=tmp[3];
            ldm4(cb + TBL*2 + off, tmp);
            blo[bt*2][0]=tmp[0]; blo[bt*2][1]=tmp[1];
            blo[bt*2+1][0]=tmp[2]; blo[bt*2+1][1]=tmp[3];
        }
#pragma unroll
        for (int mt = 0; mt < 2; mt++)
#pragma unroll
            for (int nt = 0; nt < 8; nt++) {
                mma16816(acc[mt][nt], ahi[mt], bhi[nt]);
                mma16816(acc[mt][nt], ahi[mt], blo[nt]);
                mma16816(acc[mt][nt], alo[mt], bhi[nt]);
            }
    }

#pragma unroll
    for (int mt = 0; mt < 2; mt++) {
        int m = row0 + m0w + mt*16 + lane/4;
#pragma unroll
        for (int nt = 0; nt < 8; nt++) {
            int n = col0 + n0w + nt*8 + (lane & 3)*2;
            float* Cp0 = C + (size_t)m * Sn + n;
            float* Cp1 = Cp0 + (size_t)8 * Sn;
            Cp0[0] = acc[mt][nt][0];  Cp0[1] = acc[mt][nt][1];
            Cp1[0] = acc[mt][nt][2];  Cp1[1] = acc[mt][nt][3];
        }
    }
}

// ---------------------------------------------------------------------------
// Flash attention (unchanged from R8)
// ---------------------------------------------------------------------------
#define FP 72
#define FQHI 0
#define FQLO (128*FP)
#define FSTG0 (2*128*FP)
#define FSTG_SZ (4*64*FP)
#define FKH 0
#define FKL (64*FP)
#define FVH (2*64*FP)
#define FVL (3*64*FP)
#define FLASH_SMEM ((2*128*FP + 2*4*64*FP) * 2)

__device__ __forceinline__
void flash_issue(uint32_t base, int s, size_t brow, int j0, int hoff, int t)
{
    const int jr = t >> 2, cb = (t & 3) << 4;
    const size_t so = (brow + j0 + jr) * Dn + hoff + cb;
    const uint32_t st = base + (FSTG0 + s*FSTG_SZ + jr*FP + cb) * 2;
    cpa16(st + FKH*2,      g_Kh + so);  cpa16(st + FKH*2 + 16, g_Kh + so + 8);
    cpa16(st + FKL*2,      g_Kl + so);  cpa16(st + FKL*2 + 16, g_Kl + so + 8);
    cpa16(st + FVH*2,      g_Vh + so);  cpa16(st + FVH*2 + 16, g_Vh + so + 8);
    cpa16(st + FVL*2,      g_Vl + so);  cpa16(st + FVL*2 + 16, g_Vl + so + 8);
}

__global__ __launch_bounds__(256, 2)
void flash_mma(const float* __restrict__ u)
{
    extern __shared__ uint16_t fsm[];
    const int t = threadIdx.x, lane = t & 31, w = t >> 5;
    const int q = lane >> 3, r8 = lane & 7;
    const int r = lane >> 2, qq = lane & 3;
    const int bh = blockIdx.y, b = bh >> 4, h = bh & 15;
    const int i0 = blockIdx.x << 7;

    const float* Tg = g_T + (size_t)bh*Sn*Sn;
    const uint32_t base = smem_u32(fsm);
    const size_t brow = (size_t)b * Sn;
    const int hoff = h * DHn;

    flash_issue(base, 0, brow, 0, hoff, t);
    CPA_COMMIT();

    {
        const int qr = t >> 1, cb = (t & 1) << 5;
        const size_t so = (brow + i0 + qr) * Dn + hoff + cb;
        float uu[32];
#pragma unroll
        for (int i = 0; i < 32; i += 4)
            *(float4*)(uu + i) = *(const float4*)(u + hoff + cb + i);
#pragma unroll
        for (int i = 0; i < 32; i += 8) {
            uint4 hv = *(const uint4*)(g_Qh + so + i);
            uint4 lv = *(const uint4*)(g_Ql + so + i);
            uint32_t hw[4] = {hv.x, hv.y, hv.z, hv.w};
            uint32_t lw[4] = {lv.x, lv.y, lv.z, lv.w};
#pragma unroll
            for (int k = 0; k < 4; k++) {
                float2 fh = unpack_bf2(hw[k]), fl = unpack_bf2(lw[k]);
                float y0 = (fh.x + fl.x + uu[i + 2*k])     * CSC;
                float y1 = (fh.y + fl.y + uu[i + 2*k + 1]) * CSC;
                uint32_t ho, lo_;
                cvt2(y0, y1, ho, lo_);
                *(uint32_t*)&fsm[FQHI + qr*FP + cb + i + 2*k] = ho;
                *(uint32_t*)&fsm[FQLO + qr*FP + cb + i + 2*k] = lo_;
            }
        }
    }

    float pacc[8][4];
#pragma unroll
    for (int dt = 0; dt < 8; dt++)
#pragma unroll
        for (int c = 0; c < 4; c++) pacc[dt][c] = 0.f;
    float m0 = -1e30f, m1 = -1e30f, l0 = 0.f, l1 = 0.f;

    const int i_r  = i0 + w*16 + r;
    const int i_r8 = i_r + 8;

    for (int j0 = 0; j0 < Sn; j0 += 64) {
        const int st = (j0 >> 6) & 1;
        CPA_WAIT(0);
        __syncthreads();
        if (j0 + 64 < Sn) flash_issue(base, st ^ 1, brow, j0 + 64, hoff, t);
        CPA_COMMIT();

        const uint32_t KB = base + (FSTG0 + st*FSTG_SZ) * 2;

#pragma unroll
        for (int sub = 0; sub < 2; sub++) {
            const int j1 = j0 + (sub << 5);

            float bd[4][4];
#pragma unroll
            for (int nt = 0; nt < 4; nt++) {
                int jb = j1 + nt*8 + 2*qq;
#pragma unroll
                for (int e = 0; e < 4; e++) {
                    int i = (e < 2) ? i_r : i_r8;
                    int j = jb + (e & 1);
                    int ir = (j <= i) ? i : i + 1;
                    int ic = (j <= i) ? (Sn - 1 - i + j) : (j - i - 2);
                    float v = __ldg(Tg + (size_t)ir * Sn + ic);
                    bd[nt][e] = (j == i + 1) ? 0.f : v;
                }
            }

            uint32_t qhi[4][4], qlo[4][4];
#pragma unroll
            for (int ks = 0; ks < 4; ks++) {
                int row = w*16 + r8 + (q & 1)*8;
                int col = ks*16 + (q >> 1)*8;
                uint32_t off = (uint32_t)(row*FP + col) * 2;
                ldm4(base + FQHI*2 + off, qhi[ks]);
                ldm4(base + FQLO*2 + off, qlo[ks]);
            }

            float sacc[4][4];
#pragma unroll
            for (int nt = 0; nt < 4; nt++)
#pragma unroll
                for (int c = 0; c < 4; c++) sacc[nt][c] = 0.f;

#pragma unroll
            for (int ks = 0; ks < 4; ks++) {
                uint32_t kh[4][2], kl[4][2];
#pragma unroll
                for (int bt = 0; bt < 2; bt++) {
                    int row = (sub << 5) + bt*16 + r8 + (q >> 1)*8;
                    int col = ks*16 + (q & 1)*8;
                    uint32_t off = (uint32_t)(row*FP + col) * 2;
                    uint32_t tmp[4];
                    ldm4(KB + FKH*2 + off, tmp);
                    kh[bt*2][0]=tmp[0]; kh[bt*2][1]=tmp[1];
                    kh[bt*2+1][0]=tmp[2]; kh[bt*2+1][1]=tmp[3];
                    ldm4(KB + FKL*2 + off, tmp);
                    kl[bt*2][0]=tmp[0]; kl[bt*2][1]=tmp[1];
                    kl[bt*2+1][0]=tmp[2]; kl[bt*2+1][1]=tmp[3];
                }
#pragma unroll
                for (int nt = 0; nt < 4; nt++) {
                    mma16816(sacc[nt], qhi[ks], kh[nt]);
                    mma16816(sacc[nt], qhi[ks], kl[nt]);
                    mma16816(sacc[nt], qlo[ks], kh[nt]);
                }
            }

            float ml0 = -1e30f, ml1 = -1e30f;
#pragma unroll
            for (int nt = 0; nt < 4; nt++)
#pragma unroll
                for (int e = 0; e < 4; e++) {
                    float sv = fmaf(bd[nt][e], CSC, sacc[nt][e]);
                    sacc[nt][e] = sv;
                    if (e < 2) ml0 = fmaxf(ml0, sv); else ml1 = fmaxf(ml1, sv);
                }
            ml0 = fmaxf(ml0, __shfl_xor_sync(0xFFFFFFFFu, ml0, 1));
            ml0 = fmaxf(ml0, __shfl_xor_sync(0xFFFFFFFFu, ml0, 2));
            ml1 = fmaxf(ml1, __shfl_xor_sync(0xFFFFFFFFu, ml1, 1));
            ml1 = fmaxf(ml1, __shfl_xor_sync(0xFFFFFFFFu, ml1, 2));

            float mn0 = fmaxf(m0, ml0), mn1 = fmaxf(m1, ml1);
            float f0 = ex2f(m0 - mn0), f1 = ex2f(m1 - mn1);
            m0 = mn0; m1 = mn1;

            float ls0 = 0.f, ls1 = 0.f;
#pragma unroll
            for (int nt = 0; nt < 4; nt++) {
                float p0 = ex2f(sacc[nt][0] - m0);
                float p1 = ex2f(sacc[nt][1] - m0);
                float p2 = ex2f(sacc[nt][2] - m1);
                float p3 = ex2f(sacc[nt][3] - m1);
                sacc[nt][0] = p0; sacc[nt][1] = p1; sacc[nt][2] = p2; sacc[nt][3] = p3;
                ls0 += p0 + p1;  ls1 += p2 + p3;
            }
            ls0 += __shfl_xor_sync(0xFFFFFFFFu, ls0, 1);
            ls0 += __shfl_xor_sync(0xFFFFFFFFu, ls0, 2);
            ls1 += __shfl_xor_sync(0xFFFFFFFFu, ls1, 1);
            ls1 += __shfl_xor_sync(0xFFFFFFFFu, ls1, 2);
            l0 = l0 * f0 + ls0;
            l1 = l1 * f1 + ls1;

#pragma unroll
            for (int dt = 0; dt < 8; dt++) {
                pacc[dt][0] *= f0; pacc[dt][1] *= f0;
                pacc[dt][2] *= f1; pacc[dt][3] *= f1;
            }

            uint32_t phi[2][4], plo[2][4];
#pragma unroll
            for (int ks = 0; ks < 2; ks++) {
                cvt2(sacc[2*ks][0],   sacc[2*ks][1],   phi[ks][0], plo[ks][0]);
                cvt2(sacc[2*ks][2],   sacc[2*ks][3],   phi[ks][1], plo[ks][1]);
                cvt2(sacc[2*ks+1][0], sacc[2*ks+1][1], phi[ks][2], plo[ks][2]);
                cvt2(sacc[2*ks+1][2], sacc[2*ks+1][3], phi[ks][3], plo[ks][3]);
            }

#pragma unroll
            for (int ks = 0; ks < 2; ks++) {
                uint32_t vh[8][2], vl[8][2];
#pragma unroll
                for (int dt2 = 0; dt2 < 4; dt2++) {
                    int krow = (sub << 5) + ks*16 + (lane & 7) + ((lane >> 3) & 1)*8;
                    int ncol = dt2*16 + ((lane >> 4) << 3);
                    uint32_t off = (uint32_t)(krow*FP + ncol) * 2;
                    uint32_t tmp[4];
                    ldm4t(KB + FVH*2 + off, tmp);
                    vh[dt2*2][0]=tmp[0]; vh[dt2*2][1]=tmp[1];
                    vh[dt2*2+1][0]=tmp[2]; vh[dt2*2+1][1]=tmp[3];
                    ldm4t(KB + FVL*2 + off, tmp);
                    vl[dt2*2][0]=tmp[0]; vl[dt2*2][1]=tmp[1];
                    vl[dt2*2+1][0]=tmp[2]; vl[dt2*2+1][1]=tmp[3];
                }
#pragma unroll
                for (int dt = 0; dt < 8; dt++) {
                    mma16816(pacc[dt], phi[ks], vh[dt]);
                    mma16816(pacc[dt], phi[ks], vl[dt]);
                    mma16816(pacc[dt], plo[ks], vh[dt]);
                }
            }
        }
    }

    float inv0 = 1.f / l0, inv1 = 1.f / l1;
    const size_t o_r  = (brow + i_r)  * Dn + hoff;
    const size_t o_r8 = (brow + i_r8) * Dn + hoff;
#pragma unroll
    for (int dt = 0; dt < 8; dt++) {
        int d = dt*8 + 2*qq;
        uint32_t h0, l0_;
        cvt2(pacc[dt][0]*inv0, pacc[dt][1]*inv0, h0, l0_);
        *(uint32_t*)&g_AOh[o_r + d]  = h0;
        *(uint32_t*)&g_AOl[o_r + d]  = l0_;
        cvt2(pacc[dt][2]*inv1, pacc[dt][3]*inv1, h0, l0_);
        *(uint32_t*)&g_AOh[o_r8 + d] = h0;
        *(uint32_t*)&g_AOl[o_r8 + d] = l0_;
    }
}

// ---------------------------------------------------------------------------
// Launch
// ---------------------------------------------------------------------------
extern "C" void kernel_launch(void* const* d_in, const int* in_sizes, int n_in,
                              void* d_out, int out_size)
{
    const float* x   = (const float*)d_in[0];
    const float* pos = (const float*)d_in[1];
    const float* Wq  = (const float*)d_in[2];
    const float* bq  = (const float*)d_in[3];
    const float* Wk  = (const float*)d_in[4];
    const float* bk  = (const float*)d_in[5];
    const float* Wv  = (const float*)d_in[6];
    const float* bv  = (const float*)d_in[7];
    const float* Wo  = (const float*)d_in[8];
    const float* bo  = (const float*)d_in[9];
    const float* Wkr = (const float*)d_in[10];
    const float* bkr = (const float*)d_in[11];
    const float* u   = (const float*)d_in[12];
    // d_in[13] (v) unused: GH term is per-row constant -> softmax-invariant.

    uint16_t *pxh, *pxl, *pph, *ppl;
    cudaGetSymbolAddress((void**)&pxh, g_xh);
    cudaGetSymbolAddress((void**)&pxl, g_xl);
    cudaGetSymbolAddress((void**)&pph, g_ph);
    cudaGetSymbolAddress((void**)&ppl, g_pl);

    cudaFuncSetAttribute(proj_fused,  cudaFuncAttributeMaxDynamicSharedMemorySize, GEMM_SMEM);
    cudaFuncSetAttribute(mma_gemm_wo, cudaFuncAttributeMaxDynamicSharedMemorySize, GEMM_SMEM);
    cudaFuncSetAttribute(mma_gemm_t,  cudaFuncAttributeMaxDynamicSharedMemorySize, TSMEM);
    cudaFuncSetAttribute(flash_mma,   cudaFuncAttributeMaxDynamicSharedMemorySize, FLASH_SMEM);
    cudaFuncSetAttribute(flash_mma,   cudaFuncAttributePreferredSharedMemoryCarveout, 100);

    conv_elem<<<(Bn*Sn*Dn/4 + 255)/256, 256>>>(x,   pxh, pxl, Bn*Sn*Dn/4);
    conv_elem<<<(Sn*Dn/4 + 255)/256,    256>>>(pos, pph, ppl, Sn*Dn/4);
    conv_wt<<<dim3(Dn/32, Dn/32, 5), 256>>>(Wq, Wk, Wv, Wkr, Wo);

    proj_fused<<<dim3(Dn/128, (Bn*Sn)/128, 4), 256, GEMM_SMEM>>>(bq, bk, bv, bkr);
    mma_gemm_t<<<dim3(Sn/128, Sn/128, BHn), 256, TSMEM>>>();
    flash_mma<<<dim3(Sn/128, BHn), 256, FLASH_SMEM>>>(u);
    mma_gemm_wo<<<dim3(Dn/128, (Bn*Sn)/128), 256, GEMM_SMEM>>>(bo, (float*)d_out);
}

// round 10
// speedup vs baseline: 1.0063x; 1.0063x over previous
#include <cuda_runtime.h>
#include <cuda_bf16.h>
#include <stdint.h>

// Problem constants
#define Bn  2
#define Sn  2048
#define Dn  1024
#define Hn  16
#define DHn 64
#define BHn (Bn*Hn)
#define CSC 0.18033688f   // 0.125 * log2(e)

// ---------------------------------------------------------------------------
// Scratch (static __device__) — everything bf16 hi/lo planes except g_T
// ---------------------------------------------------------------------------
__device__ uint16_t g_Qh[(size_t)Bn*Sn*Dn], g_Ql[(size_t)Bn*Sn*Dn];
__device__ uint16_t g_Kh[(size_t)Bn*Sn*Dn], g_Kl[(size_t)Bn*Sn*Dn];
__device__ uint16_t g_Vh[(size_t)Bn*Sn*Dn], g_Vl[(size_t)Bn*Sn*Dn];
__device__ uint16_t g_KRh[(size_t)Sn*Dn],   g_KRl[(size_t)Sn*Dn];
__device__ uint16_t g_xh[(size_t)Bn*Sn*Dn], g_xl[(size_t)Bn*Sn*Dn];
__device__ uint16_t g_ph[(size_t)Sn*Dn],    g_pl[(size_t)Sn*Dn];
__device__ uint16_t g_Wth[(size_t)5*Dn*Dn], g_Wtl[(size_t)5*Dn*Dn]; // q,k,v,kr,o transposed [n][k]
__device__ uint16_t g_AOh[(size_t)Bn*Sn*Dn], g_AOl[(size_t)Bn*Sn*Dn];
__device__ float    g_T [(size_t)BHn*Sn*Sn];

// ---------------------------------------------------------------------------
// Helpers
// ---------------------------------------------------------------------------
__device__ __forceinline__ uint32_t smem_u32(const void* p) {
    uint32_t a;
    asm("{ .reg .u64 t; cvta.to.shared.u64 t, %1; cvt.u32.u64 %0, t; }"
        : "=r"(a) : "l"(p));
    return a;
}
__device__ __forceinline__ void ldm4(uint32_t addr, uint32_t* r) {
    asm volatile("ldmatrix.sync.aligned.m8n8.x4.shared.b16 {%0,%1,%2,%3}, [%4];"
        : "=r"(r[0]), "=r"(r[1]), "=r"(r[2]), "=r"(r[3]) : "r"(addr));
}
__device__ __forceinline__ void ldm4t(uint32_t addr, uint32_t* r) {
    asm volatile("ldmatrix.sync.aligned.m8n8.x4.trans.shared.b16 {%0,%1,%2,%3}, [%4];"
        : "=r"(r[0]), "=r"(r[1]), "=r"(r[2]), "=r"(r[3]) : "r"(addr));
}
__device__ __forceinline__ void mma16816(float* c, const uint32_t* a, const uint32_t* b) {
    asm volatile(
        "mma.sync.aligned.m16n8k16.row.col.f32.bf16.bf16.f32 "
        "{%0,%1,%2,%3}, {%4,%5,%6,%7}, {%8,%9}, {%0,%1,%2,%3};"
        : "+f"(c[0]), "+f"(c[1]), "+f"(c[2]), "+f"(c[3])
        : "r"(a[0]), "r"(a[1]), "r"(a[2]), "r"(a[3]), "r"(b[0]), "r"(b[1]));
}
__device__ __forceinline__ float ex2f(float x) {
    float y; asm("ex2.approx.ftz.f32 %0, %1;" : "=f"(y) : "f"(x)); return y;
}
__device__ __forceinline__ void cvt2(float x0, float x1, uint32_t& hi, uint32_t& lo) {
    __nv_bfloat16 h0 = __float2bfloat16(x0);
    __nv_bfloat16 h1 = __float2bfloat16(x1);
    __nv_bfloat16 l0 = __float2bfloat16(x0 - __bfloat162float(h0));
    __nv_bfloat16 l1 = __float2bfloat16(x1 - __bfloat162float(h1));
    hi = (uint32_t)__bfloat16_as_ushort(h0) | ((uint32_t)__bfloat16_as_ushort(h1) << 16);
    lo = (uint32_t)__bfloat16_as_ushort(l0) | ((uint32_t)__bfloat16_as_ushort(l1) << 16);
}
__device__ __forceinline__ float2 unpack_bf2(uint32_t w) {
    return make_float2(
        __bfloat162float(__ushort_as_bfloat16((unsigned short)(w & 0xFFFFu))),
        __bfloat162float(__ushort_as_bfloat16((unsigned short)(w >> 16))));
}
__device__ __forceinline__ void cpa16(uint32_t dst, const void* src) {
    asm volatile("cp.async.cg.shared.global [%0], [%1], 16;" :: "r"(dst), "l"(src));
}
#define CPA_COMMIT()  asm volatile("cp.async.commit_group;" ::: "memory")
#define CPA_WAIT(N)   asm volatile("cp.async.wait_group %0;" :: "n"(N) : "memory")

// ---------------------------------------------------------------------------
// One-time plane conversion kernels
// ---------------------------------------------------------------------------
__global__ __launch_bounds__(256)
void conv_elem(const float* __restrict__ src, uint16_t* __restrict__ dh,
               uint16_t* __restrict__ dl, int n4)
{
    int i = blockIdx.x * 256 + threadIdx.x;
    if (i >= n4) return;
    float4 v = ((const float4*)src)[i];
    uint32_t h0, l0, h1, l1;
    cvt2(v.x, v.y, h0, l0);  cvt2(v.z, v.w, h1, l1);
    ((uint32_t*)dh)[i*2]   = h0;  ((uint32_t*)dh)[i*2+1] = h1;
    ((uint32_t*)dl)[i*2]   = l0;  ((uint32_t*)dl)[i*2+1] = l1;
}

__global__ __launch_bounds__(256)
void conv_wt(const float* __restrict__ Wq, const float* __restrict__ Wk,
             const float* __restrict__ Wv, const float* __restrict__ Wkr,
             const float* __restrict__ Wo)
{
    __shared__ float tile[32][33];
    const int z = blockIdx.z;
    const float* W = (z == 0) ? Wq : (z == 1) ? Wk : (z == 2) ? Wv
                   : (z == 3) ? Wkr : Wo;
    uint16_t* oh = g_Wth + (size_t)z * Dn * Dn;
    uint16_t* ol = g_Wtl + (size_t)z * Dn * Dn;
    const int k0 = blockIdx.y << 5, n0 = blockIdx.x << 5;
    const int tr = threadIdx.x >> 5, tc = threadIdx.x & 31;
#pragma unroll
    for (int i = 0; i < 4; i++)
        tile[tr + i*8][tc] = W[(size_t)(k0 + tr + i*8) * Dn + n0 + tc];
    __syncthreads();
#pragma unroll
    for (int i = 0; i < 4; i++) {
        int n = tr + i*8;
        float v = tile[tc][n];
        __nv_bfloat16 hb = __float2bfloat16(v);
        __nv_bfloat16 lb = __float2bfloat16(v - __bfloat162float(hb));
        oh[(size_t)(n0 + n) * Dn + k0 + tc] = __bfloat16_as_ushort(hb);
        ol[(size_t)(n0 + n) * Dn + k0 + tc] = __bfloat16_as_ushort(lb);
    }
}

// ---------------------------------------------------------------------------
// Plane GEMM: 256 thr, 8 warps (32x64 tiles), 5-stage cp.async pipeline,
// K-chunk 32, **product-major MMA emission (RAW distance 16)**.
// ---------------------------------------------------------------------------
#define SPITCH 40
#define GOA_HI 0
#define GOA_LO 5120
#define GOB_HI 10240
#define GOB_LO 15360
#define GSTAGE_SZ 20480
#define NSTG 5
#define GEMM_SMEM (NSTG*GSTAGE_SZ*2)

__device__ __forceinline__
void gemm_issue(uint32_t stage_b, const uint16_t* Ah, const uint16_t* Al,
                const uint16_t* Bh, const uint16_t* Bl,
                int k0, int row0, int col0, int t)
{
    const int p = t >> 7, r = t & 127;
    const uint16_t* As = (p ? Al : Ah) + (size_t)(row0 + r) * Dn + k0;
    const uint16_t* Bs = (p ? Bl : Bh) + (size_t)(col0 + r) * Dn + k0;
    uint32_t ad = stage_b + (p ? GOA_LO : GOA_HI)*2 + r*80;
    uint32_t bd = stage_b + (p ? GOB_LO : GOB_HI)*2 + r*80;
#pragma unroll
    for (int i = 0; i < 4; i++) {
        cpa16(ad + i*16, As + i*8);
        cpa16(bd + i*16, Bs + i*8);
    }
}

template<bool PLANES>
__device__ __forceinline__
void gemm_body(const uint16_t* __restrict__ Ah, const uint16_t* __restrict__ Al,
               const uint16_t* __restrict__ Bh, const uint16_t* __restrict__ Bl,
               const float* __restrict__ bias, float* __restrict__ C,
               uint16_t* __restrict__ Chi, uint16_t* __restrict__ Clo,
               int row0, int col0, uint16_t* sm)
{
    const int t = threadIdx.x, lane = t & 31, wid = t >> 5;
    const int m0w = (wid & 3) << 5, n0w = (wid >> 2) << 6;
    const int q = lane >> 3, r8 = lane & 7;
    const uint32_t sb = smem_u32(sm);
    const int NC = Dn >> 5;

#pragma unroll
    for (int s = 0; s < 4; s++) {
        gemm_issue(sb + s*GSTAGE_SZ*2, Ah, Al, Bh, Bl, s*32, row0, col0, t);
        CPA_COMMIT();
    }

    float acc[2][8][4];
#pragma unroll
    for (int mt = 0; mt < 2; mt++)
#pragma unroll
        for (int nt = 0; nt < 8; nt++)
#pragma unroll
            for (int c = 0; c < 4; c++) acc[mt][nt][c] = 0.f;

    for (int c = 0; c < NC; c++) {
        CPA_WAIT(3);
        __syncthreads();
        if (c + 4 < NC)
            gemm_issue(sb + ((c + 4) % NSTG) * GSTAGE_SZ * 2,
                       Ah, Al, Bh, Bl, (c + 4) * 32, row0, col0, t);
        CPA_COMMIT();

        const uint32_t cb = sb + (c % NSTG) * GSTAGE_SZ * 2;
#pragma unroll
        for (int ks = 0; ks < 2; ks++) {
            uint32_t ahi[2][4], alo[2][4];
#pragma unroll
            for (int mt = 0; mt < 2; mt++) {
                int row = m0w + mt*16 + r8 + (q & 1)*8;
                int col = ks*16 + (q >> 1)*8;
                uint32_t off = (uint32_t)(row*SPITCH + col) * 2;
                ldm4(cb + GOA_HI*2 + off, ahi[mt]);
                ldm4(cb + GOA_LO*2 + off, alo[mt]);
            }
            uint32_t bhi[8][2], blo[8][2];
#pragma unroll
            for (int bt = 0; bt < 4; bt++) {
                int row = n0w + bt*16 + r8 + (q >> 1)*8;
                int col = ks*16 + (q & 1)*8;
                uint32_t off = (uint32_t)(row*SPITCH + col) * 2;
                uint32_t tmp[4];
                ldm4(cb + GOB_HI*2 + off, tmp);
                bhi[bt*2][0]=tmp[0]; bhi[bt*2][1]=tmp[1];
                bhi[bt*2+1][0]=tmp[2]; bhi[bt*2+1][1]=tmp[3];
                ldm4(cb + GOB_LO*2 + off, tmp);
                blo[bt*2][0]=tmp[0]; blo[bt*2][1]=tmp[1];
                blo[bt*2+1][0]=tmp[2]; blo[bt*2+1][1]=tmp[3];
            }
            // product-major emission: RAW distance = 16 accumulators
#pragma unroll
            for (int mt = 0; mt < 2; mt++)
#pragma unroll
                for (int nt = 0; nt < 8; nt++)
                    mma16816(acc[mt][nt], ahi[mt], bhi[nt]);
#pragma unroll
            for (int mt = 0; mt < 2; mt++)
#pragma unroll
                for (int nt = 0; nt < 8; nt++)
                    mma16816(acc[mt][nt], ahi[mt], blo[nt]);
#pragma unroll
            for (int mt = 0; mt < 2; mt++)
#pragma unroll
                for (int nt = 0; nt < 8; nt++)
                    mma16816(acc[mt][nt], alo[mt], bhi[nt]);
        }
    }

#pragma unroll
    for (int mt = 0; mt < 2; mt++) {
        int m = row0 + m0w + mt*16 + lane/4;
#pragma unroll
        for (int nt = 0; nt < 8; nt++) {
            int n = col0 + n0w + nt*8 + (lane & 3)*2;
            float2 b2 = *(const float2*)(bias + n);
            float v0 = acc[mt][nt][0] + b2.x, v1 = acc[mt][nt][1] + b2.y;
            float v2 = acc[mt][nt][2] + b2.x, v3 = acc[mt][nt][3] + b2.y;
            if (PLANES) {
                uint32_t h, l;
                cvt2(v0, v1, h, l);
                *(uint32_t*)&Chi[(size_t)m*Dn + n] = h;
                *(uint32_t*)&Clo[(size_t)m*Dn + n] = l;
                cvt2(v2, v3, h, l);
                *(uint32_t*)&Chi[(size_t)(m+8)*Dn + n] = h;
                *(uint32_t*)&Clo[(size_t)(m+8)*Dn + n] = l;
            } else {
                float* Cp0 = C + (size_t)m * Dn + n;
                float* Cp1 = Cp0 + (size_t)8 * Dn;
                Cp0[0] = v0;  Cp0[1] = v1;
                Cp1[0] = v2;  Cp1[1] = v3;
            }
        }
    }
}

__global__ __launch_bounds__(256, 1)
void proj_fused(const float* __restrict__ bq, const float* __restrict__ bk,
                const float* __restrict__ bv, const float* __restrict__ bkr)
{
    extern __shared__ uint16_t gsm[];
    const int z = blockIdx.z;
    const int row0 = blockIdx.y << 7, col0 = blockIdx.x << 7;
    if (z == 3 && row0 >= Sn) return;
    const uint16_t *Ah, *Al; const float* bias; uint16_t *Chi, *Clo;
    if (z < 3) { Ah = g_xh; Al = g_xl; } else { Ah = g_ph; Al = g_pl; }
    if      (z == 0) { bias = bq;  Chi = g_Qh;  Clo = g_Ql;  }
    else if (z == 1) { bias = bk;  Chi = g_Kh;  Clo = g_Kl;  }
    else if (z == 2) { bias = bv;  Chi = g_Vh;  Clo = g_Vl;  }
    else             { bias = bkr; Chi = g_KRh; Clo = g_KRl; }
    const uint16_t* Bh = g_Wth + (size_t)z * Dn * Dn;
    const uint16_t* Bl = g_Wtl + (size_t)z * Dn * Dn;
    gemm_body<true>(Ah, Al, Bh, Bl, bias, nullptr, Chi, Clo, row0, col0, gsm);
}

__global__ __launch_bounds__(256, 1)
void mma_gemm_wo(const float* __restrict__ bias, float* __restrict__ C)
{
    extern __shared__ uint16_t gsm[];
    gemm_body<false>(g_AOh, g_AOl,
                     g_Wth + (size_t)4 * Dn * Dn, g_Wtl + (size_t)4 * Dn * Dn,
                     bias, C, nullptr, nullptr,
                     blockIdx.y << 7, blockIdx.x << 7, gsm);
}

// ---------------------------------------------------------------------------
// NT GEMM from planes:  T[bh] = Q_bh [S,64] @ KR_h^T  (product-major MMAs)
// ---------------------------------------------------------------------------
#define TP 72
#define TAH 0
#define TAL (128*TP)
#define TBH (2*128*TP)
#define TBL (3*128*TP)
#define TSMEM (4*128*TP*2)

__global__ __launch_bounds__(256, 1)
void mma_gemm_t()
{
    extern __shared__ uint16_t tsm[];
    const int t = threadIdx.x, lane = t & 31, wid = t >> 5;
    const int bh = blockIdx.z, b = bh >> 4, h = bh & 15;
    const int row0 = blockIdx.y << 7, col0 = blockIdx.x << 7;
    const int m0w = (wid & 3) << 5, n0w = (wid >> 2) << 6;
    const int q = lane >> 3, r8 = lane & 7;

    float* C = g_T + (size_t)bh * Sn * Sn;

    {
        const int r = t >> 1, c = (t & 1) << 5;
        const size_t soA = ((size_t)b*Sn + row0 + r) * Dn + h*DHn + c;
        const size_t soB = ((size_t)col0 + r) * Dn + h*DHn + c;
        const uint32_t sb = smem_u32(tsm);
        uint32_t da = sb + (TAH + r*TP + c)*2;
        uint32_t dl = sb + (TAL + r*TP + c)*2;
        uint32_t db = sb + (TBH + r*TP + c)*2;
        uint32_t dbl = sb + (TBL + r*TP + c)*2;
#pragma unroll
        for (int i = 0; i < 4; i++) {
            cpa16(da + i*16,  g_Qh  + soA + i*8);
            cpa16(dl + i*16,  g_Ql  + soA + i*8);
            cpa16(db + i*16,  g_KRh + soB + i*8);
            cpa16(dbl + i*16, g_KRl + soB + i*8);
        }
        CPA_COMMIT();
        CPA_WAIT(0);
    }
    __syncthreads();

    float acc[2][8][4];
#pragma unroll
    for (int mt = 0; mt < 2; mt++)
#pragma unroll
        for (int nt = 0; nt < 8; nt++)
#pragma unroll
            for (int c = 0; c < 4; c++) acc[mt][nt][c] = 0.f;

    const uint32_t cb = smem_u32(tsm);
#pragma unroll
    for (int ks = 0; ks < 4; ks++) {
        uint32_t ahi[2][4], alo[2][4];
#pragma unroll
        for (int mt = 0; mt < 2; mt++) {
            int row = m0w + mt*16 + r8 + (q & 1)*8;
            int col = ks*16 + (q >> 1)*8;
            uint32_t off = (uint32_t)(row*TP + col) * 2;
            ldm4(cb + TAH*2 + off, ahi[mt]);
            ldm4(cb + TAL*2 + off, alo[mt]);
        }
        uint32_t bhi[8][2], blo[8][2];
#pragma unroll
        for (int bt = 0; bt < 4; bt++) {
            int row = n0w + bt*16 + r8 + (q >> 1)*8;
            int col = ks*16 + (q & 1)*8;
            uint32_t off = (uint32_t)(row*TP + col) * 2;
            uint32_t tmp[4];
            ldm4(cb + TBH*2 + off, tmp);
            bhi[bt*2][0]=tmp[0]; bhi[bt*2][1]=tmp[1];
            bhi[bt*2+1][0]=tmp[2]; bhi[bt*2+1][1]=tmp[3];
            ldm4(cb + TBL*2 + off, tmp);
            blo[bt*2][0]=tmp[0]; blo[bt*2][1]=tmp[1];
            blo[bt*2+1][0]=tmp[2]; blo[bt*2+1][1]=tmp[3];
        }
        // product-major
#pragma unroll
        for (int mt = 0; mt < 2; mt++)
#pragma unroll
            for (int nt = 0; nt < 8; nt++)
                mma16816(acc[mt][nt], ahi[mt], bhi[nt]);
#pragma unroll
        for (int mt = 0; mt < 2; mt++)
#pragma unroll
            for (int nt = 0; nt < 8; nt++)
                mma16816(acc[mt][nt], ahi[mt], blo[nt]);
#pragma unroll
        for (int mt = 0; mt < 2; mt++)
#pragma unroll
            for (int nt = 0; nt < 8; nt++)
                mma16816(acc[mt][nt], alo[mt], bhi[nt]);
    }

#pragma unroll
    for (int mt = 0; mt < 2; mt++) {
        int m = row0 + m0w + mt*16 + lane/4;
#pragma unroll
        for (int nt = 0; nt < 8; nt++) {
            int n = col0 + n0w + nt*8 + (lane & 3)*2;
            float* Cp0 = C + (size_t)m * Sn + n;
            float* Cp1 = Cp0 + (size_t)8 * Sn;
            Cp0[0] = acc[mt][nt][0];  Cp0[1] = acc[mt][nt][1];
            Cp1[0] = acc[mt][nt][2];  Cp1[1] = acc[mt][nt][3];
        }
    }
}

// ---------------------------------------------------------------------------
// Flash attention: product-major MMAs; otherwise unchanged from R8
// ---------------------------------------------------------------------------
#define FP 72
#define FQHI 0
#define FQLO (128*FP)
#define FSTG0 (2*128*FP)
#define FSTG_SZ (4*64*FP)
#define FKH 0
#define FKL (64*FP)
#define FVH (2*64*FP)
#define FVL (3*64*FP)
#define FLASH_SMEM ((2*128*FP + 2*4*64*FP) * 2)

__device__ __forceinline__
void flash_issue(uint32_t base, int s, size_t brow, int j0, int hoff, int t)
{
    const int jr = t >> 2, cb = (t & 3) << 4;
    const size_t so = (brow + j0 + jr) * Dn + hoff + cb;
    const uint32_t st = base + (FSTG0 + s*FSTG_SZ + jr*FP + cb) * 2;
    cpa16(st + FKH*2,      g_Kh + so);  cpa16(st + FKH*2 + 16, g_Kh + so + 8);
    cpa16(st + FKL*2,      g_Kl + so);  cpa16(st + FKL*2 + 16, g_Kl + so + 8);
    cpa16(st + FVH*2,      g_Vh + so);  cpa16(st + FVH*2 + 16, g_Vh + so + 8);
    cpa16(st + FVL*2,      g_Vl + so);  cpa16(st + FVL*2 + 16, g_Vl + so + 8);
}

__global__ __launch_bounds__(256, 2)
void flash_mma(const float* __restrict__ u)
{
    extern __shared__ uint16_t fsm[];
    const int t = threadIdx.x, lane = t & 31, w = t >> 5;
    const int q = lane >> 3, r8 = lane & 7;
    const int r = lane >> 2, qq = lane & 3;
    const int bh = blockIdx.y, b = bh >> 4, h = bh & 15;
    const int i0 = blockIdx.x << 7;

    const float* Tg = g_T + (size_t)bh*Sn*Sn;
    const uint32_t base = smem_u32(fsm);
    const size_t brow = (size_t)b * Sn;
    const int hoff = h * DHn;

    flash_issue(base, 0, brow, 0, hoff, t);
    CPA_COMMIT();

    {
        const int qr = t >> 1, cb = (t & 1) << 5;
        const size_t so = (brow + i0 + qr) * Dn + hoff + cb;
        float uu[32];
#pragma unroll
        for (int i = 0; i < 32; i += 4)
            *(float4*)(uu + i) = *(const float4*)(u + hoff + cb + i);
#pragma unroll
        for (int i = 0; i < 32; i += 8) {
            uint4 hv = *(const uint4*)(g_Qh + so + i);
            uint4 lv = *(const uint4*)(g_Ql + so + i);
            uint32_t hw[4] = {hv.x, hv.y, hv.z, hv.w};
            uint32_t lw[4] = {lv.x, lv.y, lv.z, lv.w};
#pragma unroll
            for (int k = 0; k < 4; k++) {
                float2 fh = unpack_bf2(hw[k]), fl = unpack_bf2(lw[k]);
                float y0 = (fh.x + fl.x + uu[i + 2*k])     * CSC;
                float y1 = (fh.y + fl.y + uu[i + 2*k + 1]) * CSC;
                uint32_t ho, lo_;
                cvt2(y0, y1, ho, lo_);
                *(uint32_t*)&fsm[FQHI + qr*FP + cb + i + 2*k] = ho;
                *(uint32_t*)&fsm[FQLO + qr*FP + cb + i + 2*k] = lo_;
            }
        }
    }

    float pacc[8][4];
#pragma unroll
    for (int dt = 0; dt < 8; dt++)
#pragma unroll
        for (int c = 0; c < 4; c++) pacc[dt][c] = 0.f;
    float m0 = -1e30f, m1 = -1e30f, l0 = 0.f, l1 = 0.f;

    const int i_r  = i0 + w*16 + r;
    const int i_r8 = i_r + 8;

    for (int j0 = 0; j0 < Sn; j0 += 64) {
        const int st = (j0 >> 6) & 1;
        CPA_WAIT(0);
        __syncthreads();
        if (j0 + 64 < Sn) flash_issue(base, st ^ 1, brow, j0 + 64, hoff, t);
        CPA_COMMIT();

        const uint32_t KB = base + (FSTG0 + st*FSTG_SZ) * 2;

#pragma unroll
        for (int sub = 0; sub < 2; sub++) {
            const int j1 = j0 + (sub << 5);

            float bd[4][4];
#pragma unroll
            for (int nt = 0; nt < 4; nt++) {
                int jb = j1 + nt*8 + 2*qq;
#pragma unroll
                for (int e = 0; e < 4; e++) {
                    int i = (e < 2) ? i_r : i_r8;
                    int j = jb + (e & 1);
                    int ir = (j <= i) ? i : i + 1;
                    int ic = (j <= i) ? (Sn - 1 - i + j) : (j - i - 2);
                    float v = __ldg(Tg + (size_t)ir * Sn + ic);
                    bd[nt][e] = (j == i + 1) ? 0.f : v;
                }
            }

            uint32_t qhi[4][4], qlo[4][4];
#pragma unroll
            for (int ks = 0; ks < 4; ks++) {
                int row = w*16 + r8 + (q & 1)*8;
                int col = ks*16 + (q >> 1)*8;
                uint32_t off = (uint32_t)(row*FP + col) * 2;
                ldm4(base + FQHI*2 + off, qhi[ks]);
                ldm4(base + FQLO*2 + off, qlo[ks]);
            }

            float sacc[4][4];
#pragma unroll
            for (int nt = 0; nt < 4; nt++)
#pragma unroll
                for (int c = 0; c < 4; c++) sacc[nt][c] = 0.f;

#pragma unroll
            for (int ks = 0; ks < 4; ks++) {
                uint32_t kh[4][2], kl[4][2];
#pragma unroll
                for (int bt = 0; bt < 2; bt++) {
                    int row = (sub << 5) + bt*16 + r8 + (q >> 1)*8;
                    int col = ks*16 + (q & 1)*8;
                    uint32_t off = (uint32_t)(row*FP + col) * 2;
                    uint32_t tmp[4];
                    ldm4(KB + FKH*2 + off, tmp);
                    kh[bt*2][0]=tmp[0]; kh[bt*2][1]=tmp[1];
                    kh[bt*2+1][0]=tmp[2]; kh[bt*2+1][1]=tmp[3];
                    ldm4(KB + FKL*2 + off, tmp);
                    kl[bt*2][0]=tmp[0]; kl[bt*2][1]=tmp[1];
                    kl[bt*2+1][0]=tmp[2]; kl[bt*2+1][1]=tmp[3];
                }
                // product-major: RAW distance 4
#pragma unroll
                for (int nt = 0; nt < 4; nt++)
                    mma16816(sacc[nt], qhi[ks], kh[nt]);
#pragma unroll
                for (int nt = 0; nt < 4; nt++)
                    mma16816(sacc[nt], qhi[ks], kl[nt]);
#pragma unroll
                for (int nt = 0; nt < 4; nt++)
                    mma16816(sacc[nt], qlo[ks], kh[nt]);
            }

            float ml0 = -1e30f, ml1 = -1e30f;
#pragma unroll
            for (int nt = 0; nt < 4; nt++)
#pragma unroll
                for (int e = 0; e < 4; e++) {
                    float sv = fmaf(bd[nt][e], CSC, sacc[nt][e]);
                    sacc[nt][e] = sv;
                    if (e < 2) ml0 = fmaxf(ml0, sv); else ml1 = fmaxf(ml1, sv);
                }
            ml0 = fmaxf(ml0, __shfl_xor_sync(0xFFFFFFFFu, ml0, 1));
            ml0 = fmaxf(ml0, __shfl_xor_sync(0xFFFFFFFFu, ml0, 2));
            ml1 = fmaxf(ml1, __shfl_xor_sync(0xFFFFFFFFu, ml1, 1));
            ml1 = fmaxf(ml1, __shfl_xor_sync(0xFFFFFFFFu, ml1, 2));

            float mn0 = fmaxf(m0, ml0), mn1 = fmaxf(m1, ml1);
            float f0 = ex2f(m0 - mn0), f1 = ex2f(m1 - mn1);
            m0 = mn0; m1 = mn1;

            float ls0 = 0.f, ls1 = 0.f;
#pragma unroll
            for (int nt = 0; nt < 4; nt++) {
                float p0 = ex2f(sacc[nt][0] - m0);
                float p1 = ex2f(sacc[nt][1] - m0);
                float p2 = ex2f(sacc[nt][2] - m1);
                float p3 = ex2f(sacc[nt][3] - m1);
                sacc[nt][0] = p0; sacc[nt][1] = p1; sacc[nt][2] = p2; sacc[nt][3] = p3;
                ls0 += p0 + p1;  ls1 += p2 + p3;
            }
            ls0 += __shfl_xor_sync(0xFFFFFFFFu, ls0, 1);
            ls0 += __shfl_xor_sync(0xFFFFFFFFu, ls0, 2);
            ls1 += __shfl_xor_sync(0xFFFFFFFFu, ls1, 1);
            ls1 += __shfl_xor_sync(0xFFFFFFFFu, ls1, 2);
            l0 = l0 * f0 + ls0;
            l1 = l1 * f1 + ls1;

#pragma unroll
            for (int dt = 0; dt < 8; dt++) {
                pacc[dt][0] *= f0; pacc[dt][1] *= f0;
                pacc[dt][2] *= f1; pacc[dt][3] *= f1;
            }

            uint32_t phi[2][4], plo[2][4];
#pragma unroll
            for (int ks = 0; ks < 2; ks++) {
                cvt2(sacc[2*ks][0],   sacc[2*ks][1],   phi[ks][0], plo[ks][0]);
                cvt2(sacc[2*ks][2],   sacc[2*ks][3],   phi[ks][1], plo[ks][1]);
                cvt2(sacc[2*ks+1][0], sacc[2*ks+1][1], phi[ks][2], plo[ks][2]);
                cvt2(sacc[2*ks+1][2], sacc[2*ks+1][3], phi[ks][3], plo[ks][3]);
            }

#pragma unroll
            for (int ks = 0; ks < 2; ks++) {
                uint32_t vh[8][2], vl[8][2];
#pragma unroll
                for (int dt2 = 0; dt2 < 4; dt2++) {
                    int krow = (sub << 5) + ks*16 + (lane & 7) + ((lane >> 3) & 1)*8;
                    int ncol = dt2*16 + ((lane >> 4) << 3);
                    uint32_t off = (uint32_t)(krow*FP + ncol) * 2;
                    uint32_t tmp[4];
                    ldm4t(KB + FVH*2 + off, tmp);
                    vh[dt2*2][0]=tmp[0]; vh[dt2*2][1]=tmp[1];
                    vh[dt2*2+1][0]=tmp[2]; vh[dt2*2+1][1]=tmp[3];
                    ldm4t(KB + FVL*2 + off, tmp);
                    vl[dt2*2][0]=tmp[0]; vl[dt2*2][1]=tmp[1];
                    vl[dt2*2+1][0]=tmp[2]; vl[dt2*2+1][1]=tmp[3];
                }
                // product-major: RAW distance 8
#pragma unroll
                for (int dt = 0; dt < 8; dt++)
                    mma16816(pacc[dt], phi[ks], vh[dt]);
#pragma unroll
                for (int dt = 0; dt < 8; dt++)
                    mma16816(pacc[dt], phi[ks], vl[dt]);
#pragma unroll
                for (int dt = 0; dt < 8; dt++)
                    mma16816(pacc[dt], plo[ks], vh[dt]);
            }
        }
    }

    float inv0 = 1.f / l0, inv1 = 1.f / l1;
    const size_t o_r  = (brow + i_r)  * Dn + hoff;
    const size_t o_r8 = (brow + i_r8) * Dn + hoff;
#pragma unroll
    for (int dt = 0; dt < 8; dt++) {
        int d = dt*8 + 2*qq;
        uint32_t h0, l0_;
        cvt2(pacc[dt][0]*inv0, pacc[dt][1]*inv0, h0, l0_);
        *(uint32_t*)&g_AOh[o_r + d]  = h0;
        *(uint32_t*)&g_AOl[o_r + d]  = l0_;
        cvt2(pacc[dt][2]*inv1, pacc[dt][3]*inv1, h0, l0_);
        *(uint32_t*)&g_AOh[o_r8 + d] = h0;
        *(uint32_t*)&g_AOl[o_r8 + d] = l0_;
    }
}

// ---------------------------------------------------------------------------
// Launch
// ---------------------------------------------------------------------------
extern "C" void kernel_launch(void* const* d_in, const int* in_sizes, int n_in,
                              void* d_out, int out_size)
{
    const float* x   = (const float*)d_in[0];
    const float* pos = (const float*)d_in[1];
    const float* Wq  = (const float*)d_in[2];
    const float* bq  = (const float*)d_in[3];
    const float* Wk  = (const float*)d_in[4];
    const float* bk  = (const float*)d_in[5];
    const float* Wv  = (const float*)d_in[6];
    const float* bv  = (const float*)d_in[7];
    const float* Wo  = (const float*)d_in[8];
    const float* bo  = (const float*)d_in[9];
    const float* Wkr = (const float*)d_in[10];
    const float* bkr = (const float*)d_in[11];
    const float* u   = (const float*)d_in[12];
    // d_in[13] (v) unused: GH term is per-row constant -> softmax-invariant.

    uint16_t *pxh, *pxl, *pph, *ppl;
    cudaGetSymbolAddress((void**)&pxh, g_xh);
    cudaGetSymbolAddress((void**)&pxl, g_xl);
    cudaGetSymbolAddress((void**)&pph, g_ph);
    cudaGetSymbolAddress((void**)&ppl, g_pl);

    cudaFuncSetAttribute(proj_fused,  cudaFuncAttributeMaxDynamicSharedMemorySize, GEMM_SMEM);
    cudaFuncSetAttribute(mma_gemm_wo, cudaFuncAttributeMaxDynamicSharedMemorySize, GEMM_SMEM);
    cudaFuncSetAttribute(mma_gemm_t,  cudaFuncAttributeMaxDynamicSharedMemorySize, TSMEM);
    cudaFuncSetAttribute(flash_mma,   cudaFuncAttributeMaxDynamicSharedMemorySize, FLASH_SMEM);
    cudaFuncSetAttribute(flash_mma,   cudaFuncAttributePreferredSharedMemoryCarveout, 100);

    conv_elem<<<(Bn*Sn*Dn/4 + 255)/256, 256>>>(x,   pxh, pxl, Bn*Sn*Dn/4);
    conv_elem<<<(Sn*Dn/4 + 255)/256,    256>>>(pos, pph, ppl, Sn*Dn/4);
    conv_wt<<<dim3(Dn/32, Dn/32, 5), 256>>>(Wq, Wk, Wv, Wkr, Wo);

    proj_fused<<<dim3(Dn/128, (Bn*Sn)/128, 4), 256, GEMM_SMEM>>>(bq, bk, bv, bkr);
    mma_gemm_t<<<dim3(Sn/128, Sn/128, BHn), 256, TSMEM>>>();
    flash_mma<<<dim3(Sn/128, BHn), 256, FLASH_SMEM>>>(u);
    mma_gemm_wo<<<dim3(Dn/128, (Bn*Sn)/128), 256, GEMM_SMEM>>>(bo, (float*)d_out);
}

// round 11
// speedup vs baseline: 1.5065x; 1.4971x over previous
#include <cuda_runtime.h>
#include <cuda_fp16.h>
#include <stdint.h>

// Problem constants
#define Bn  2
#define Sn  2048
#define Dn  1024
#define Hn  16
#define DHn 64
#define BHn (Bn*Hn)
#define CSC 0.18033688f   // 0.125 * log2(e)

// ---------------------------------------------------------------------------
// Scratch — single fp16 planes (tensor inputs), fp32 T
// ---------------------------------------------------------------------------
__device__ uint16_t g_Q [(size_t)Bn*Sn*Dn];
__device__ uint16_t g_K [(size_t)Bn*Sn*Dn];
__device__ uint16_t g_V [(size_t)Bn*Sn*Dn];
__device__ uint16_t g_KR[(size_t)Sn*Dn];
__device__ uint16_t g_x [(size_t)Bn*Sn*Dn];
__device__ uint16_t g_p [(size_t)Sn*Dn];
__device__ uint16_t g_Wt[(size_t)5*Dn*Dn];      // q,k,v,kr,o transposed [n][k]
__device__ uint16_t g_AO[(size_t)Bn*Sn*Dn];
__device__ float    g_T [(size_t)BHn*Sn*Sn];

// ---------------------------------------------------------------------------
// Helpers
// ---------------------------------------------------------------------------
__device__ __forceinline__ uint32_t smem_u32(const void* p) {
    uint32_t a;
    asm("{ .reg .u64 t; cvta.to.shared.u64 t, %1; cvt.u32.u64 %0, t; }"
        : "=r"(a) : "l"(p));
    return a;
}
__device__ __forceinline__ void ldm4(uint32_t addr, uint32_t* r) {
    asm volatile("ldmatrix.sync.aligned.m8n8.x4.shared.b16 {%0,%1,%2,%3}, [%4];"
        : "=r"(r[0]), "=r"(r[1]), "=r"(r[2]), "=r"(r[3]) : "r"(addr));
}
__device__ __forceinline__ void ldm4t(uint32_t addr, uint32_t* r) {
    asm volatile("ldmatrix.sync.aligned.m8n8.x4.trans.shared.b16 {%0,%1,%2,%3}, [%4];"
        : "=r"(r[0]), "=r"(r[1]), "=r"(r[2]), "=r"(r[3]) : "r"(addr));
}
__device__ __forceinline__ void mma_h(float* c, const uint32_t* a, const uint32_t* b) {
    asm volatile(
        "mma.sync.aligned.m16n8k16.row.col.f32.f16.f16.f32 "
        "{%0,%1,%2,%3}, {%4,%5,%6,%7}, {%8,%9}, {%0,%1,%2,%3};"
        : "+f"(c[0]), "+f"(c[1]), "+f"(c[2]), "+f"(c[3])
        : "r"(a[0]), "r"(a[1]), "r"(a[2]), "r"(a[3]), "r"(b[0]), "r"(b[1]));
}
__device__ __forceinline__ float ex2f(float x) {
    float y; asm("ex2.approx.ftz.f32 %0, %1;" : "=f"(y) : "f"(x)); return y;
}
// pack two fp32 -> f16x2 (lo = x0, hi = x1)
__device__ __forceinline__ uint32_t cvt2h(float x0, float x1) {
    uint32_t w;
    asm("cvt.rn.f16x2.f32 %0, %1, %2;" : "=r"(w) : "f"(x1), "f"(x0));
    return w;
}
__device__ __forceinline__ float2 unpack_h2(uint32_t w) {
    __half2 h = *reinterpret_cast<__half2*>(&w);
    return __half22float2(h);
}
__device__ __forceinline__ void cpa16(uint32_t dst, const void* src) {
    asm volatile("cp.async.cg.shared.global [%0], [%1], 16;" :: "r"(dst), "l"(src));
}
#define CPA_COMMIT()  asm volatile("cp.async.commit_group;" ::: "memory")
#define CPA_WAIT(N)   asm volatile("cp.async.wait_group %0;" :: "n"(N) : "memory")

// ---------------------------------------------------------------------------
// One-time fp16 conversion kernels
// ---------------------------------------------------------------------------
__global__ __launch_bounds__(256)
void conv_elem(const float* __restrict__ src, uint16_t* __restrict__ d, int n4)
{
    int i = blockIdx.x * 256 + threadIdx.x;
    if (i >= n4) return;
    float4 v = ((const float4*)src)[i];
    ((uint32_t*)d)[i*2]     = cvt2h(v.x, v.y);
    ((uint32_t*)d)[i*2 + 1] = cvt2h(v.z, v.w);
}

__global__ __launch_bounds__(256)
void conv_wt(const float* __restrict__ Wq, const float* __restrict__ Wk,
             const float* __restrict__ Wv, const float* __restrict__ Wkr,
             const float* __restrict__ Wo)
{
    __shared__ float tile[32][33];
    const int z = blockIdx.z;
    const float* W = (z == 0) ? Wq : (z == 1) ? Wk : (z == 2) ? Wv
                   : (z == 3) ? Wkr : Wo;
    uint16_t* o = g_Wt + (size_t)z * Dn * Dn;
    const int k0 = blockIdx.y << 5, n0 = blockIdx.x << 5;
    const int tr = threadIdx.x >> 5, tc = threadIdx.x & 31;
#pragma unroll
    for (int i = 0; i < 4; i++)
        tile[tr + i*8][tc] = W[(size_t)(k0 + tr + i*8) * Dn + n0 + tc];
    __syncthreads();
#pragma unroll
    for (int i = 0; i < 4; i++) {
        int n = tr + i*8;
        __half hv = __float2half_rn(tile[tc][n]);
        o[(size_t)(n0 + n) * Dn + k0 + tc] = *reinterpret_cast<uint16_t*>(&hv);
    }
}

// ---------------------------------------------------------------------------
// fp16 plane GEMM: C[M,1024] = A @ B^T (+bias). 256 thr, 8 warps (32x64),
// 5-stage cp.async pipeline, K-chunk 32, single-product MMA.
// ---------------------------------------------------------------------------
#define SPITCH 40
#define GOA 0
#define GOB 5120
#define GSTAGE_SZ 10240                  // b16 per stage (20480 B)
#define NSTG 5
#define GEMM_SMEM (NSTG*GSTAGE_SZ*2)     // 102400 bytes

__device__ __forceinline__
void gemm_issue(uint32_t stage_b, const uint16_t* A, const uint16_t* B,
                int k0, int row0, int col0, int t)
{
    const int p = t >> 7, r = t & 127;
    const uint16_t* S = (p ? B + (size_t)(col0 + r) * Dn
                           : A + (size_t)(row0 + r) * Dn) + k0;
    uint32_t d = stage_b + (p ? GOB : GOA)*2 + r*80;
#pragma unroll
    for (int i = 0; i < 4; i++)
        cpa16(d + i*16, S + i*8);
}

template<bool PLANE>
__device__ __forceinline__
void gemm_body(const uint16_t* __restrict__ A, const uint16_t* __restrict__ B,
               const float* __restrict__ bias, float* __restrict__ C,
               uint16_t* __restrict__ Cp,
               int row0, int col0, uint16_t* sm)
{
    const int t = threadIdx.x, lane = t & 31, wid = t >> 5;
    const int m0w = (wid & 3) << 5, n0w = (wid >> 2) << 6;
    const int q = lane >> 3, r8 = lane & 7;
    const uint32_t sb = smem_u32(sm);
    const int NC = Dn >> 5;

#pragma unroll
    for (int s = 0; s < 4; s++) {
        gemm_issue(sb + s*GSTAGE_SZ*2, A, B, s*32, row0, col0, t);
        CPA_COMMIT();
    }

    float acc[2][8][4];
#pragma unroll
    for (int mt = 0; mt < 2; mt++)
#pragma unroll
        for (int nt = 0; nt < 8; nt++)
#pragma unroll
            for (int c = 0; c < 4; c++) acc[mt][nt][c] = 0.f;

    for (int c = 0; c < NC; c++) {
        CPA_WAIT(3);
        __syncthreads();
        if (c + 4 < NC)
            gemm_issue(sb + ((c + 4) % NSTG) * GSTAGE_SZ * 2,
                       A, B, (c + 4) * 32, row0, col0, t);
        CPA_COMMIT();

        const uint32_t cb = sb + (c % NSTG) * GSTAGE_SZ * 2;
#pragma unroll
        for (int ks = 0; ks < 2; ks++) {
            uint32_t af[2][4];
#pragma unroll
            for (int mt = 0; mt < 2; mt++) {
                int row = m0w + mt*16 + r8 + (q & 1)*8;
                int col = ks*16 + (q >> 1)*8;
                ldm4(cb + GOA*2 + (uint32_t)(row*SPITCH + col)*2, af[mt]);
            }
            uint32_t bf[8][2];
#pragma unroll
            for (int bt = 0; bt < 4; bt++) {
                int row = n0w + bt*16 + r8 + (q >> 1)*8;
                int col = ks*16 + (q & 1)*8;
                uint32_t tmp[4];
                ldm4(cb + GOB*2 + (uint32_t)(row*SPITCH + col)*2, tmp);
                bf[bt*2][0]=tmp[0]; bf[bt*2][1]=tmp[1];
                bf[bt*2+1][0]=tmp[2]; bf[bt*2+1][1]=tmp[3];
            }
#pragma unroll
            for (int mt = 0; mt < 2; mt++)
#pragma unroll
                for (int nt = 0; nt < 8; nt++)
                    mma_h(acc[mt][nt], af[mt], bf[nt]);
        }
    }

#pragma unroll
    for (int mt = 0; mt < 2; mt++) {
        int m = row0 + m0w + mt*16 + lane/4;
#pragma unroll
        for (int nt = 0; nt < 8; nt++) {
            int n = col0 + n0w + nt*8 + (lane & 3)*2;
            float2 b2 = *(const float2*)(bias + n);
            float v0 = acc[mt][nt][0] + b2.x, v1 = acc[mt][nt][1] + b2.y;
            float v2 = acc[mt][nt][2] + b2.x, v3 = acc[mt][nt][3] + b2.y;
            if (PLANE) {
                *(uint32_t*)&Cp[(size_t)m*Dn + n]     = cvt2h(v0, v1);
                *(uint32_t*)&Cp[(size_t)(m+8)*Dn + n] = cvt2h(v2, v3);
            } else {
                float* Cp0 = C + (size_t)m * Dn + n;
                float* Cp1 = Cp0 + (size_t)8 * Dn;
                Cp0[0] = v0;  Cp0[1] = v1;
                Cp1[0] = v2;  Cp1[1] = v3;
            }
        }
    }
}

__global__ __launch_bounds__(256, 1)
void proj_fused(const float* __restrict__ bq, const float* __restrict__ bk,
                const float* __restrict__ bv, const float* __restrict__ bkr)
{
    extern __shared__ uint16_t gsm[];
    const int z = blockIdx.z;
    const int row0 = blockIdx.y << 7, col0 = blockIdx.x << 7;
    if (z == 3 && row0 >= Sn) return;
    const uint16_t* A = (z < 3) ? g_x : g_p;
    const float* bias; uint16_t* Cp;
    if      (z == 0) { bias = bq;  Cp = g_Q;  }
    else if (z == 1) { bias = bk;  Cp = g_K;  }
    else if (z == 2) { bias = bv;  Cp = g_V;  }
    else             { bias = bkr; Cp = g_KR; }
    gemm_body<true>(A, g_Wt + (size_t)z * Dn * Dn, bias, nullptr, Cp,
                    row0, col0, gsm);
}

__global__ __launch_bounds__(256, 1)
void mma_gemm_wo(const float* __restrict__ bias, float* __restrict__ C)
{
    extern __shared__ uint16_t gsm[];
    gemm_body<false>(g_AO, g_Wt + (size_t)4 * Dn * Dn, bias, C, nullptr,
                     blockIdx.y << 7, blockIdx.x << 7, gsm);
}

// ---------------------------------------------------------------------------
// NT GEMM (fp16 single):  T[bh] = Q_bh [S,64] @ KR_h^T
// ---------------------------------------------------------------------------
#define TP 72
#define TA 0
#define TB (128*TP)
#define TSMEM (2*128*TP*2)

__global__ __launch_bounds__(256, 1)
void mma_gemm_t()
{
    extern __shared__ uint16_t tsm[];
    const int t = threadIdx.x, lane = t & 31, wid = t >> 5;
    const int bh = blockIdx.z, b = bh >> 4, h = bh & 15;
    const int row0 = blockIdx.y << 7, col0 = blockIdx.x << 7;
    const int m0w = (wid & 3) << 5, n0w = (wid >> 2) << 6;
    const int q = lane >> 3, r8 = lane & 7;

    float* C = g_T + (size_t)bh * Sn * Sn;

    {
        const int r = t >> 1, c = (t & 1) << 5;
        const size_t soA = ((size_t)b*Sn + row0 + r) * Dn + h*DHn + c;
        const size_t soB = ((size_t)col0 + r) * Dn + h*DHn + c;
        const uint32_t sb = smem_u32(tsm);
        uint32_t da = sb + (TA + r*TP + c)*2;
        uint32_t db = sb + (TB + r*TP + c)*2;
#pragma unroll
        for (int i = 0; i < 4; i++) {
            cpa16(da + i*16, g_Q  + soA + i*8);
            cpa16(db + i*16, g_KR + soB + i*8);
        }
        CPA_COMMIT();
        CPA_WAIT(0);
    }
    __syncthreads();

    float acc[2][8][4];
#pragma unroll
    for (int mt = 0; mt < 2; mt++)
#pragma unroll
        for (int nt = 0; nt < 8; nt++)
#pragma unroll
            for (int c = 0; c < 4; c++) acc[mt][nt][c] = 0.f;

    const uint32_t cb = smem_u32(tsm);
#pragma unroll
    for (int ks = 0; ks < 4; ks++) {
        uint32_t af[2][4];
#pragma unroll
        for (int mt = 0; mt < 2; mt++) {
            int row = m0w + mt*16 + r8 + (q & 1)*8;
            int col = ks*16 + (q >> 1)*8;
            ldm4(cb + TA*2 + (uint32_t)(row*TP + col)*2, af[mt]);
        }
        uint32_t bf[8][2];
#pragma unroll
        for (int bt = 0; bt < 4; bt++) {
            int row = n0w + bt*16 + r8 + (q >> 1)*8;
            int col = ks*16 + (q & 1)*8;
            uint32_t tmp[4];
            ldm4(cb + TB*2 + (uint32_t)(row*TP + col)*2, tmp);
            bf[bt*2][0]=tmp[0]; bf[bt*2][1]=tmp[1];
            bf[bt*2+1][0]=tmp[2]; bf[bt*2+1][1]=tmp[3];
        }
#pragma unroll
        for (int mt = 0; mt < 2; mt++)
#pragma unroll
            for (int nt = 0; nt < 8; nt++)
                mma_h(acc[mt][nt], af[mt], bf[nt]);
    }

#pragma unroll
    for (int mt = 0; mt < 2; mt++) {
        int m = row0 + m0w + mt*16 + lane/4;
#pragma unroll
        for (int nt = 0; nt < 8; nt++) {
            int n = col0 + n0w + nt*8 + (lane & 3)*2;
            float* Cp0 = C + (size_t)m * Sn + n;
            float* Cp1 = Cp0 + (size_t)8 * Sn;
            Cp0[0] = acc[mt][nt][0];  Cp0[1] = acc[mt][nt][1];
            Cp1[0] = acc[mt][nt][2];  Cp1[1] = acc[mt][nt][3];
        }
    }
}

// ---------------------------------------------------------------------------
// Flash attention (fp16 single): cp.async double-buffered K/V, exp2 softmax.
// ---------------------------------------------------------------------------
#define FP 72
#define FQ 0
#define FSTG0 (128*FP)
#define FSTG_SZ (2*64*FP)
#define FK 0
#define FV (64*FP)
#define FLASH_SMEM ((128*FP + 2*2*64*FP) * 2)   // 55296 bytes

__device__ __forceinline__
void flash_issue(uint32_t base, int s, size_t brow, int j0, int hoff, int t)
{
    const int jr = t >> 2, cb = (t & 3) << 4;
    const size_t so = (brow + j0 + jr) * Dn + hoff + cb;
    const uint32_t st = base + (FSTG0 + s*FSTG_SZ + jr*FP + cb) * 2;
    cpa16(st + FK*2,      g_K + so);  cpa16(st + FK*2 + 16, g_K + so + 8);
    cpa16(st + FV*2,      g_V + so);  cpa16(st + FV*2 + 16, g_V + so + 8);
}

__global__ __launch_bounds__(256, 2)
void flash_mma(const float* __restrict__ u)
{
    extern __shared__ uint16_t fsm[];
    const int t = threadIdx.x, lane = t & 31, w = t >> 5;
    const int q = lane >> 3, r8 = lane & 7;
    const int r = lane >> 2, qq = lane & 3;
    const int bh = blockIdx.y, b = bh >> 4, h = bh & 15;
    const int i0 = blockIdx.x << 7;

    const float* Tg = g_T + (size_t)bh*Sn*Sn;
    const uint32_t base = smem_u32(fsm);
    const size_t brow = (size_t)b * Sn;
    const int hoff = h * DHn;

    flash_issue(base, 0, brow, 0, hoff, t);
    CPA_COMMIT();

    // stage Q: (q + u)*CSC -> fp16
    {
        const int qr = t >> 1, cb = (t & 1) << 5;
        const size_t so = (brow + i0 + qr) * Dn + hoff + cb;
        float uu[32];
#pragma unroll
        for (int i = 0; i < 32; i += 4)
            *(float4*)(uu + i) = *(const float4*)(u + hoff + cb + i);
#pragma unroll
        for (int i = 0; i < 32; i += 8) {
            uint4 hv = *(const uint4*)(g_Q + so + i);
            uint32_t hw[4] = {hv.x, hv.y, hv.z, hv.w};
#pragma unroll
            for (int k = 0; k < 4; k++) {
                float2 f = unpack_h2(hw[k]);
                *(uint32_t*)&fsm[FQ + qr*FP + cb + i + 2*k] =
                    cvt2h((f.x + uu[i + 2*k]) * CSC, (f.y + uu[i + 2*k + 1]) * CSC);
            }
        }
    }

    float pacc[8][4];
#pragma unroll
    for (int dt = 0; dt < 8; dt++)
#pragma unroll
        for (int c = 0; c < 4; c++) pacc[dt][c] = 0.f;
    float m0 = -1e30f, m1 = -1e30f, l0 = 0.f, l1 = 0.f;

    const int i_r  = i0 + w*16 + r;
    const int i_r8 = i_r + 8;

    for (int j0 = 0; j0 < Sn; j0 += 64) {
        const int st = (j0 >> 6) & 1;
        CPA_WAIT(0);
        __syncthreads();
        if (j0 + 64 < Sn) flash_issue(base, st ^ 1, brow, j0 + 64, hoff, t);
        CPA_COMMIT();

        const uint32_t KB = base + (FSTG0 + st*FSTG_SZ) * 2;

#pragma unroll
        for (int sub = 0; sub < 2; sub++) {
            const int j1 = j0 + (sub << 5);

            // BD prefetch (overlaps S-MMAs)
            float bd[4][4];
#pragma unroll
            for (int nt = 0; nt < 4; nt++) {
                int jb = j1 + nt*8 + 2*qq;
#pragma unroll
                for (int e = 0; e < 4; e++) {
                    int i = (e < 2) ? i_r : i_r8;
                    int j = jb + (e & 1);
                    int ir = (j <= i) ? i : i + 1;
                    int ic = (j <= i) ? (Sn - 1 - i + j) : (j - i - 2);
                    float v = __ldg(Tg + (size_t)ir * Sn + ic);
                    bd[nt][e] = (j == i + 1) ? 0.f : v;
                }
            }

            uint32_t qf[4][4];
#pragma unroll
            for (int ks = 0; ks < 4; ks++) {
                int row = w*16 + r8 + (q & 1)*8;
                int col = ks*16 + (q >> 1)*8;
                ldm4(base + FQ*2 + (uint32_t)(row*FP + col)*2, qf[ks]);
            }

            float sacc[4][4];
#pragma unroll
            for (int nt = 0; nt < 4; nt++)
#pragma unroll
                for (int c = 0; c < 4; c++) sacc[nt][c] = 0.f;

#pragma unroll
            for (int ks = 0; ks < 4; ks++) {
                uint32_t kf[4][2];
#pragma unroll
                for (int bt = 0; bt < 2; bt++) {
                    int row = (sub << 5) + bt*16 + r8 + (q >> 1)*8;
                    int col = ks*16 + (q & 1)*8;
                    uint32_t tmp[4];
                    ldm4(KB + FK*2 + (uint32_t)(row*FP + col)*2, tmp);
                    kf[bt*2][0]=tmp[0]; kf[bt*2][1]=tmp[1];
                    kf[bt*2+1][0]=tmp[2]; kf[bt*2+1][1]=tmp[3];
                }
#pragma unroll
                for (int nt = 0; nt < 4; nt++)
                    mma_h(sacc[nt], qf[ks], kf[nt]);
            }

            // add BD (exp2 domain), online softmax
            float ml0 = -1e30f, ml1 = -1e30f;
#pragma unroll
            for (int nt = 0; nt < 4; nt++)
#pragma unroll
                for (int e = 0; e < 4; e++) {
                    float sv = fmaf(bd[nt][e], CSC, sacc[nt][e]);
                    sacc[nt][e] = sv;
                    if (e < 2) ml0 = fmaxf(ml0, sv); else ml1 = fmaxf(ml1, sv);
                }
            ml0 = fmaxf(ml0, __shfl_xor_sync(0xFFFFFFFFu, ml0, 1));
            ml0 = fmaxf(ml0, __shfl_xor_sync(0xFFFFFFFFu, ml0, 2));
            ml1 = fmaxf(ml1, __shfl_xor_sync(0xFFFFFFFFu, ml1, 1));
            ml1 = fmaxf(ml1, __shfl_xor_sync(0xFFFFFFFFu, ml1, 2));

            float mn0 = fmaxf(m0, ml0), mn1 = fmaxf(m1, ml1);
            float f0 = ex2f(m0 - mn0), f1 = ex2f(m1 - mn1);
            m0 = mn0; m1 = mn1;

            float ls0 = 0.f, ls1 = 0.f;
#pragma unroll
            for (int nt = 0; nt < 4; nt++) {
                float p0 = ex2f(sacc[nt][0] - m0);
                float p1 = ex2f(sacc[nt][1] - m0);
                float p2 = ex2f(sacc[nt][2] - m1);
                float p3 = ex2f(sacc[nt][3] - m1);
                sacc[nt][0] = p0; sacc[nt][1] = p1; sacc[nt][2] = p2; sacc[nt][3] = p3;
                ls0 += p0 + p1;  ls1 += p2 + p3;
            }
            ls0 += __shfl_xor_sync(0xFFFFFFFFu, ls0, 1);
            ls0 += __shfl_xor_sync(0xFFFFFFFFu, ls0, 2);
            ls1 += __shfl_xor_sync(0xFFFFFFFFu, ls1, 1);
            ls1 += __shfl_xor_sync(0xFFFFFFFFu, ls1, 2);
            l0 = l0 * f0 + ls0;
            l1 = l1 * f1 + ls1;

#pragma unroll
            for (int dt = 0; dt < 8; dt++) {
                pacc[dt][0] *= f0; pacc[dt][1] *= f0;
                pacc[dt][2] *= f1; pacc[dt][3] *= f1;
            }

            // pack P (C-frag pair -> A-frag), fp16
            uint32_t pf[2][4];
#pragma unroll
            for (int ks = 0; ks < 2; ks++) {
                pf[ks][0] = cvt2h(sacc[2*ks][0],   sacc[2*ks][1]);
                pf[ks][1] = cvt2h(sacc[2*ks][2],   sacc[2*ks][3]);
                pf[ks][2] = cvt2h(sacc[2*ks+1][0], sacc[2*ks+1][1]);
                pf[ks][3] = cvt2h(sacc[2*ks+1][2], sacc[2*ks+1][3]);
            }

            // pacc += P @ V (B-frags via ldmatrix.trans of row-major V)
#pragma unroll
            for (int ks = 0; ks < 2; ks++) {
                uint32_t vf[8][2];
#pragma unroll
                for (int dt2 = 0; dt2 < 4; dt2++) {
                    int krow = (sub << 5) + ks*16 + (lane & 7) + ((lane >> 3) & 1)*8;
                    int ncol = dt2*16 + ((lane >> 4) << 3);
                    uint32_t tmp[4];
                    ldm4t(KB + FV*2 + (uint32_t)(krow*FP + ncol)*2, tmp);
                    vf[dt2*2][0]=tmp[0]; vf[dt2*2][1]=tmp[1];
                    vf[dt2*2+1][0]=tmp[2]; vf[dt2*2+1][1]=tmp[3];
                }
#pragma unroll
                for (int dt = 0; dt < 8; dt++)
                    mma_h(pacc[dt], pf[ks], vf[dt]);
            }
        }
    }

    // normalize & write AO (fp16 plane)
    float inv0 = 1.f / l0, inv1 = 1.f / l1;
    const size_t o_r  = (brow + i_r)  * Dn + hoff;
    const size_t o_r8 = (brow + i_r8) * Dn + hoff;
#pragma unroll
    for (int dt = 0; dt < 8; dt++) {
        int d = dt*8 + 2*qq;
        *(uint32_t*)&g_AO[o_r + d]  = cvt2h(pacc[dt][0]*inv0, pacc[dt][1]*inv0);
        *(uint32_t*)&g_AO[o_r8 + d] = cvt2h(pacc[dt][2]*inv1, pacc[dt][3]*inv1);
    }
}

// ---------------------------------------------------------------------------
// Launch
// ---------------------------------------------------------------------------
extern "C" void kernel_launch(void* const* d_in, const int* in_sizes, int n_in,
                              void* d_out, int out_size)
{
    const float* x   = (const float*)d_in[0];
    const float* pos = (const float*)d_in[1];
    const float* Wq  = (const float*)d_in[2];
    const float* bq  = (const float*)d_in[3];
    const float* Wk  = (const float*)d_in[4];
    const float* bk  = (const float*)d_in[5];
    const float* Wv  = (const float*)d_in[6];
    const float* bv  = (const float*)d_in[7];
    const float* Wo  = (const float*)d_in[8];
    const float* bo  = (const float*)d_in[9];
    const float* Wkr = (const float*)d_in[10];
    const float* bkr = (const float*)d_in[11];
    const float* u   = (const float*)d_in[12];
    // d_in[13] (v) unused: GH term is per-row constant -> softmax-invariant.

    uint16_t *px, *pp;
    cudaGetSymbolAddress((void**)&px, g_x);
    cudaGetSymbolAddress((void**)&pp, g_p);

    cudaFuncSetAttribute(proj_fused,  cudaFuncAttributeMaxDynamicSharedMemorySize, GEMM_SMEM);
    cudaFuncSetAttribute(mma_gemm_wo, cudaFuncAttributeMaxDynamicSharedMemorySize, GEMM_SMEM);
    cudaFuncSetAttribute(mma_gemm_t,  cudaFuncAttributeMaxDynamicSharedMemorySize, TSMEM);
    cudaFuncSetAttribute(flash_mma,   cudaFuncAttributeMaxDynamicSharedMemorySize, FLASH_SMEM);
    cudaFuncSetAttribute(flash_mma,   cudaFuncAttributePreferredSharedMemoryCarveout, 100);

    conv_elem<<<(Bn*Sn*Dn/4 + 255)/256, 256>>>(x,   px, Bn*Sn*Dn/4);
    conv_elem<<<(Sn*Dn/4 + 255)/256,    256>>>(pos, pp, Sn*Dn/4);
    conv_wt<<<dim3(Dn/32, Dn/32, 5), 256>>>(Wq, Wk, Wv, Wkr, Wo);

    proj_fused<<<dim3(Dn/128, (Bn*Sn)/128, 4), 256, GEMM_SMEM>>>(bq, bk, bv, bkr);
    mma_gemm_t<<<dim3(Sn/128, Sn/128, BHn), 256, TSMEM>>>();
    flash_mma<<<dim3(Sn/128, BHn), 256, FLASH_SMEM>>>(u);
    mma_gemm_wo<<<dim3(Dn/128, (Bn*Sn)/128), 256, GEMM_SMEM>>>(bo, (float*)d_out);
}

// round 12
// speedup vs baseline: 1.7274x; 1.1467x over previous
#include <cuda_runtime.h>
#include <cuda_fp16.h>
#include <stdint.h>

// Problem constants
#define Bn  2
#define Sn  2048
#define Dn  1024
#define Hn  16
#define DHn 64
#define BHn (Bn*Hn)
#define CSC 0.18033688f   // 0.125 * log2(e)

// ---------------------------------------------------------------------------
// Scratch — single fp16 planes (tensor inputs), fp32 T
// ---------------------------------------------------------------------------
__device__ uint16_t g_Q [(size_t)Bn*Sn*Dn];
__device__ uint16_t g_K [(size_t)Bn*Sn*Dn];
__device__ uint16_t g_V [(size_t)Bn*Sn*Dn];
__device__ uint16_t g_KR[(size_t)Sn*Dn];
__device__ uint16_t g_x [(size_t)Bn*Sn*Dn];
__device__ uint16_t g_p [(size_t)Sn*Dn];
__device__ uint16_t g_Wt[(size_t)5*Dn*Dn];      // q,k,v,kr,o transposed [n][k]
__device__ uint16_t g_AO[(size_t)Bn*Sn*Dn];
__device__ float    g_T [(size_t)BHn*Sn*Sn];

// ---------------------------------------------------------------------------
// Helpers
// ---------------------------------------------------------------------------
__device__ __forceinline__ uint32_t smem_u32(const void* p) {
    uint32_t a;
    asm("{ .reg .u64 t; cvta.to.shared.u64 t, %1; cvt.u32.u64 %0, t; }"
        : "=r"(a) : "l"(p));
    return a;
}
__device__ __forceinline__ void ldm4(uint32_t addr, uint32_t* r) {
    asm volatile("ldmatrix.sync.aligned.m8n8.x4.shared.b16 {%0,%1,%2,%3}, [%4];"
        : "=r"(r[0]), "=r"(r[1]), "=r"(r[2]), "=r"(r[3]) : "r"(addr));
}
__device__ __forceinline__ void ldm4t(uint32_t addr, uint32_t* r) {
    asm volatile("ldmatrix.sync.aligned.m8n8.x4.trans.shared.b16 {%0,%1,%2,%3}, [%4];"
        : "=r"(r[0]), "=r"(r[1]), "=r"(r[2]), "=r"(r[3]) : "r"(addr));
}
__device__ __forceinline__ void mma_h(float* c, const uint32_t* a, const uint32_t* b) {
    asm volatile(
        "mma.sync.aligned.m16n8k16.row.col.f32.f16.f16.f32 "
        "{%0,%1,%2,%3}, {%4,%5,%6,%7}, {%8,%9}, {%0,%1,%2,%3};"
        : "+f"(c[0]), "+f"(c[1]), "+f"(c[2]), "+f"(c[3])
        : "r"(a[0]), "r"(a[1]), "r"(a[2]), "r"(a[3]), "r"(b[0]), "r"(b[1]));
}
__device__ __forceinline__ float ex2f(float x) {
    float y; asm("ex2.approx.ftz.f32 %0, %1;" : "=f"(y) : "f"(x)); return y;
}
__device__ __forceinline__ uint32_t cvt2h(float x0, float x1) {
    uint32_t w;
    asm("cvt.rn.f16x2.f32 %0, %1, %2;" : "=r"(w) : "f"(x1), "f"(x0));
    return w;
}
__device__ __forceinline__ float2 unpack_h2(uint32_t w) {
    __half2 h = *reinterpret_cast<__half2*>(&w);
    return __half22float2(h);
}
__device__ __forceinline__ void cpa16(uint32_t dst, const void* src) {
    asm volatile("cp.async.cg.shared.global [%0], [%1], 16;" :: "r"(dst), "l"(src));
}
#define CPA_COMMIT()  asm volatile("cp.async.commit_group;" ::: "memory")
#define CPA_WAIT(N)   asm volatile("cp.async.wait_group %0;" :: "n"(N) : "memory")

// ---------------------------------------------------------------------------
// One-time fp16 conversion kernels
// ---------------------------------------------------------------------------
__global__ __launch_bounds__(256)
void conv_elem(const float* __restrict__ src, uint16_t* __restrict__ d, int n4)
{
    int i = blockIdx.x * 256 + threadIdx.x;
    if (i >= n4) return;
    float4 v = ((const float4*)src)[i];
    ((uint32_t*)d)[i*2]     = cvt2h(v.x, v.y);
    ((uint32_t*)d)[i*2 + 1] = cvt2h(v.z, v.w);
}

__global__ __launch_bounds__(256)
void conv_wt(const float* __restrict__ Wq, const float* __restrict__ Wk,
             const float* __restrict__ Wv, const float* __restrict__ Wkr,
             const float* __restrict__ Wo)
{
    __shared__ float tile[32][33];
    const int z = blockIdx.z;
    const float* W = (z == 0) ? Wq : (z == 1) ? Wk : (z == 2) ? Wv
                   : (z == 3) ? Wkr : Wo;
    uint16_t* o = g_Wt + (size_t)z * Dn * Dn;
    const int k0 = blockIdx.y << 5, n0 = blockIdx.x << 5;
    const int tr = threadIdx.x >> 5, tc = threadIdx.x & 31;
#pragma unroll
    for (int i = 0; i < 4; i++)
        tile[tr + i*8][tc] = W[(size_t)(k0 + tr + i*8) * Dn + n0 + tc];
    __syncthreads();
#pragma unroll
    for (int i = 0; i < 4; i++) {
        int n = tr + i*8;
        __half hv = __float2half_rn(tile[tc][n]);
        o[(size_t)(n0 + n) * Dn + k0 + tc] = *reinterpret_cast<uint16_t*>(&hv);
    }
}

// ---------------------------------------------------------------------------
// fp16 plane GEMM: 256 thr, 8 warps (32x64), 5-stage cp.async, 2 blocks/SM.
// ---------------------------------------------------------------------------
#define SPITCH 40
#define GOA 0
#define GOB 5120
#define GSTAGE_SZ 10240                  // b16 per stage
#define NSTG 5
#define GEMM_SMEM (NSTG*GSTAGE_SZ*2)     // 102400 bytes

__device__ __forceinline__
void gemm_issue(uint32_t stage_b, const uint16_t* A, const uint16_t* B,
                int k0, int row0, int col0, int t)
{
    const int p = t >> 7, r = t & 127;
    const uint16_t* S = (p ? B + (size_t)(col0 + r) * Dn
                           : A + (size_t)(row0 + r) * Dn) + k0;
    uint32_t d = stage_b + (p ? GOB : GOA)*2 + r*80;
#pragma unroll
    for (int i = 0; i < 4; i++)
        cpa16(d + i*16, S + i*8);
}

template<bool PLANE>
__device__ __forceinline__
void gemm_body(const uint16_t* __restrict__ A, const uint16_t* __restrict__ B,
               const float* __restrict__ bias, float* __restrict__ C,
               uint16_t* __restrict__ Cp,
               int row0, int col0, uint16_t* sm)
{
    const int t = threadIdx.x, lane = t & 31, wid = t >> 5;
    const int m0w = (wid & 3) << 5, n0w = (wid >> 2) << 6;
    const int q = lane >> 3, r8 = lane & 7;
    const uint32_t sb = smem_u32(sm);
    const int NC = Dn >> 5;

#pragma unroll
    for (int s = 0; s < 4; s++) {
        gemm_issue(sb + s*GSTAGE_SZ*2, A, B, s*32, row0, col0, t);
        CPA_COMMIT();
    }

    float acc[2][8][4];
#pragma unroll
    for (int mt = 0; mt < 2; mt++)
#pragma unroll
        for (int nt = 0; nt < 8; nt++)
#pragma unroll
            for (int c = 0; c < 4; c++) acc[mt][nt][c] = 0.f;

    for (int c = 0; c < NC; c++) {
        CPA_WAIT(3);
        __syncthreads();
        if (c + 4 < NC)
            gemm_issue(sb + ((c + 4) % NSTG) * GSTAGE_SZ * 2,
                       A, B, (c + 4) * 32, row0, col0, t);
        CPA_COMMIT();

        const uint32_t cb = sb + (c % NSTG) * GSTAGE_SZ * 2;
#pragma unroll
        for (int ks = 0; ks < 2; ks++) {
            uint32_t af[2][4];
#pragma unroll
            for (int mt = 0; mt < 2; mt++) {
                int row = m0w + mt*16 + r8 + (q & 1)*8;
                int col = ks*16 + (q >> 1)*8;
                ldm4(cb + GOA*2 + (uint32_t)(row*SPITCH + col)*2, af[mt]);
            }
            uint32_t bf[8][2];
#pragma unroll
            for (int bt = 0; bt < 4; bt++) {
                int row = n0w + bt*16 + r8 + (q >> 1)*8;
                int col = ks*16 + (q & 1)*8;
                uint32_t tmp[4];
                ldm4(cb + GOB*2 + (uint32_t)(row*SPITCH + col)*2, tmp);
                bf[bt*2][0]=tmp[0]; bf[bt*2][1]=tmp[1];
                bf[bt*2+1][0]=tmp[2]; bf[bt*2+1][1]=tmp[3];
            }
#pragma unroll
            for (int mt = 0; mt < 2; mt++)
#pragma unroll
                for (int nt = 0; nt < 8; nt++)
                    mma_h(acc[mt][nt], af[mt], bf[nt]);
        }
    }

#pragma unroll
    for (int mt = 0; mt < 2; mt++) {
        int m = row0 + m0w + mt*16 + lane/4;
#pragma unroll
        for (int nt = 0; nt < 8; nt++) {
            int n = col0 + n0w + nt*8 + (lane & 3)*2;
            float2 b2 = *(const float2*)(bias + n);
            float v0 = acc[mt][nt][0] + b2.x, v1 = acc[mt][nt][1] + b2.y;
            float v2 = acc[mt][nt][2] + b2.x, v3 = acc[mt][nt][3] + b2.y;
            if (PLANE) {
                *(uint32_t*)&Cp[(size_t)m*Dn + n]     = cvt2h(v0, v1);
                *(uint32_t*)&Cp[(size_t)(m+8)*Dn + n] = cvt2h(v2, v3);
            } else {
                float* Cp0 = C + (size_t)m * Dn + n;
                float* Cp1 = Cp0 + (size_t)8 * Dn;
                Cp0[0] = v0;  Cp0[1] = v1;
                Cp1[0] = v2;  Cp1[1] = v3;
            }
        }
    }
}

__global__ __launch_bounds__(256, 2)
void proj_fused(const float* __restrict__ bq, const float* __restrict__ bk,
                const float* __restrict__ bv, const float* __restrict__ bkr)
{
    extern __shared__ uint16_t gsm[];
    const int z = blockIdx.z;
    const int row0 = blockIdx.y << 7, col0 = blockIdx.x << 7;
    if (z == 3 && row0 >= Sn) return;
    const uint16_t* A = (z < 3) ? g_x : g_p;
    const float* bias; uint16_t* Cp;
    if      (z == 0) { bias = bq;  Cp = g_Q;  }
    else if (z == 1) { bias = bk;  Cp = g_K;  }
    else if (z == 2) { bias = bv;  Cp = g_V;  }
    else             { bias = bkr; Cp = g_KR; }
    gemm_body<true>(A, g_Wt + (size_t)z * Dn * Dn, bias, nullptr, Cp,
                    row0, col0, gsm);
}

__global__ __launch_bounds__(256, 2)
void mma_gemm_wo(const float* __restrict__ bias, float* __restrict__ C)
{
    extern __shared__ uint16_t gsm[];
    gemm_body<false>(g_AO, g_Wt + (size_t)4 * Dn * Dn, bias, C, nullptr,
                     blockIdx.y << 7, blockIdx.x << 7, gsm);
}

// ---------------------------------------------------------------------------
// NT GEMM (fp16):  T[bh] = Q_bh [S,64] @ KR_h^T.  2 blocks/SM.
// ---------------------------------------------------------------------------
#define TP 72
#define TA 0
#define TB (128*TP)
#define TSMEM (2*128*TP*2)

__global__ __launch_bounds__(256, 2)
void mma_gemm_t()
{
    extern __shared__ uint16_t tsm[];
    const int t = threadIdx.x, lane = t & 31, wid = t >> 5;
    const int bh = blockIdx.z, b = bh >> 4, h = bh & 15;
    const int row0 = blockIdx.y << 7, col0 = blockIdx.x << 7;
    const int m0w = (wid & 3) << 5, n0w = (wid >> 2) << 6;
    const int q = lane >> 3, r8 = lane & 7;

    float* C = g_T + (size_t)bh * Sn * Sn;

    {
        const int r = t >> 1, c = (t & 1) << 5;
        const size_t soA = ((size_t)b*Sn + row0 + r) * Dn + h*DHn + c;
        const size_t soB = ((size_t)col0 + r) * Dn + h*DHn + c;
        const uint32_t sb = smem_u32(tsm);
        uint32_t da = sb + (TA + r*TP + c)*2;
        uint32_t db = sb + (TB + r*TP + c)*2;
#pragma unroll
        for (int i = 0; i < 4; i++) {
            cpa16(da + i*16, g_Q  + soA + i*8);
            cpa16(db + i*16, g_KR + soB + i*8);
        }
        CPA_COMMIT();
        CPA_WAIT(0);
    }
    __syncthreads();

    float acc[2][8][4];
#pragma unroll
    for (int mt = 0; mt < 2; mt++)
#pragma unroll
        for (int nt = 0; nt < 8; nt++)
#pragma unroll
            for (int c = 0; c < 4; c++) acc[mt][nt][c] = 0.f;

    const uint32_t cb = smem_u32(tsm);
#pragma unroll
    for (int ks = 0; ks < 4; ks++) {
        uint32_t af[2][4];
#pragma unroll
        for (int mt = 0; mt < 2; mt++) {
            int row = m0w + mt*16 + r8 + (q & 1)*8;
            int col = ks*16 + (q >> 1)*8;
            ldm4(cb + TA*2 + (uint32_t)(row*TP + col)*2, af[mt]);
        }
        uint32_t bf[8][2];
#pragma unroll
        for (int bt = 0; bt < 4; bt++) {
            int row = n0w + bt*16 + r8 + (q >> 1)*8;
            int col = ks*16 + (q & 1)*8;
            uint32_t tmp[4];
            ldm4(cb + TB*2 + (uint32_t)(row*TP + col)*2, tmp);
            bf[bt*2][0]=tmp[0]; bf[bt*2][1]=tmp[1];
            bf[bt*2+1][0]=tmp[2]; bf[bt*2+1][1]=tmp[3];
        }
#pragma unroll
        for (int mt = 0; mt < 2; mt++)
#pragma unroll
            for (int nt = 0; nt < 8; nt++)
                mma_h(acc[mt][nt], af[mt], bf[nt]);
    }

#pragma unroll
    for (int mt = 0; mt < 2; mt++) {
        int m = row0 + m0w + mt*16 + lane/4;
#pragma unroll
        for (int nt = 0; nt < 8; nt++) {
            int n = col0 + n0w + nt*8 + (lane & 3)*2;
            float* Cp0 = C + (size_t)m * Sn + n;
            float* Cp1 = Cp0 + (size_t)8 * Sn;
            Cp0[0] = acc[mt][nt][0];  Cp0[1] = acc[mt][nt][1];
            Cp1[0] = acc[mt][nt][2];  Cp1[1] = acc[mt][nt][3];
        }
    }
}

// ---------------------------------------------------------------------------
// Flash attention (fp16): 3-stage cp.async K/V ring (wait_group 1),
// Q-fragments hoisted out of the main loop, exp2 softmax, 2 blocks/SM.
// ---------------------------------------------------------------------------
#define FP 72
#define FQ 0
#define FSTG0 (128*FP)
#define FSTG_SZ (2*64*FP)
#define FK 0
#define FV (64*FP)
#define FNS 3
#define FLASH_SMEM ((128*FP + FNS*2*64*FP) * 2)   // 73728 bytes

__device__ __forceinline__
void flash_issue(uint32_t base, int s, size_t brow, int j0, int hoff, int t)
{
    const int jr = t >> 2, cb = (t & 3) << 4;
    const size_t so = (brow + j0 + jr) * Dn + hoff + cb;
    const uint32_t st = base + (FSTG0 + s*FSTG_SZ + jr*FP + cb) * 2;
    cpa16(st + FK*2,      g_K + so);  cpa16(st + FK*2 + 16, g_K + so + 8);
    cpa16(st + FV*2,      g_V + so);  cpa16(st + FV*2 + 16, g_V + so + 8);
}

__global__ __launch_bounds__(256, 2)
void flash_mma(const float* __restrict__ u)
{
    extern __shared__ uint16_t fsm[];
    const int t = threadIdx.x, lane = t & 31, w = t >> 5;
    const int q = lane >> 3, r8 = lane & 7;
    const int r = lane >> 2, qq = lane & 3;
    const int bh = blockIdx.y, b = bh >> 4, h = bh & 15;
    const int i0 = blockIdx.x << 7;

    const float* Tg = g_T + (size_t)bh*Sn*Sn;
    const uint32_t base = smem_u32(fsm);
    const size_t brow = (size_t)b * Sn;
    const int hoff = h * DHn;

    // prefetch K/V tiles 0 and 1
    flash_issue(base, 0, brow, 0,  hoff, t);
    CPA_COMMIT();
    flash_issue(base, 1, brow, 64, hoff, t);
    CPA_COMMIT();

    // stage Q: (q + u)*CSC -> fp16
    {
        const int qr = t >> 1, cb = (t & 1) << 5;
        const size_t so = (brow + i0 + qr) * Dn + hoff + cb;
        float uu[32];
#pragma unroll
        for (int i = 0; i < 32; i += 4)
            *(float4*)(uu + i) = *(const float4*)(u + hoff + cb + i);
#pragma unroll
        for (int i = 0; i < 32; i += 8) {
            uint4 hv = *(const uint4*)(g_Q + so + i);
            uint32_t hw[4] = {hv.x, hv.y, hv.z, hv.w};
#pragma unroll
            for (int k = 0; k < 4; k++) {
                float2 f = unpack_h2(hw[k]);
                *(uint32_t*)&fsm[FQ + qr*FP + cb + i + 2*k] =
                    cvt2h((f.x + uu[i + 2*k]) * CSC, (f.y + uu[i + 2*k + 1]) * CSC);
            }
        }
    }
    __syncthreads();

    // hoisted Q fragments (register-resident for whole kernel)
    uint32_t qf[4][4];
#pragma unroll
    for (int ks = 0; ks < 4; ks++) {
        int row = w*16 + r8 + (q & 1)*8;
        int col = ks*16 + (q >> 1)*8;
        ldm4(base + FQ*2 + (uint32_t)(row*FP + col)*2, qf[ks]);
    }

    float pacc[8][4];
#pragma unroll
    for (int dt = 0; dt < 8; dt++)
#pragma unroll
        for (int c = 0; c < 4; c++) pacc[dt][c] = 0.f;
    float m0 = -1e30f, m1 = -1e30f, l0 = 0.f, l1 = 0.f;

    const int i_r  = i0 + w*16 + r;
    const int i_r8 = i_r + 8;

    for (int j0 = 0; j0 < Sn; j0 += 64) {
        const int ti = j0 >> 6;
        CPA_WAIT(1);
        __syncthreads();
        if (j0 + 128 < Sn) flash_issue(base, (ti + 2) % FNS, brow, j0 + 128, hoff, t);
        CPA_COMMIT();

        const uint32_t KB = base + (FSTG0 + (ti % FNS)*FSTG_SZ) * 2;

#pragma unroll
        for (int sub = 0; sub < 2; sub++) {
            const int j1 = j0 + (sub << 5);

            // BD prefetch (overlaps S-MMAs)
            float bd[4][4];
#pragma unroll
            for (int nt = 0; nt < 4; nt++) {
                int jb = j1 + nt*8 + 2*qq;
#pragma unroll
                for (int e = 0; e < 4; e++) {
                    int i = (e < 2) ? i_r : i_r8;
                    int j = jb + (e & 1);
                    int ir = (j <= i) ? i : i + 1;
                    int ic = (j <= i) ? (Sn - 1 - i + j) : (j - i - 2);
                    float v = __ldg(Tg + (size_t)ir * Sn + ic);
                    bd[nt][e] = (j == i + 1) ? 0.f : v;
                }
            }

            float sacc[4][4];
#pragma unroll
            for (int nt = 0; nt < 4; nt++)
#pragma unroll
                for (int c = 0; c < 4; c++) sacc[nt][c] = 0.f;

#pragma unroll
            for (int ks = 0; ks < 4; ks++) {
                uint32_t kf[4][2];
#pragma unroll
                for (int bt = 0; bt < 2; bt++) {
                    int row = (sub << 5) + bt*16 + r8 + (q >> 1)*8;
                    int col = ks*16 + (q & 1)*8;
                    uint32_t tmp[4];
                    ldm4(KB + FK*2 + (uint32_t)(row*FP + col)*2, tmp);
                    kf[bt*2][0]=tmp[0]; kf[bt*2][1]=tmp[1];
                    kf[bt*2+1][0]=tmp[2]; kf[bt*2+1][1]=tmp[3];
                }
#pragma unroll
                for (int nt = 0; nt < 4; nt++)
                    mma_h(sacc[nt], qf[ks], kf[nt]);
            }

            // add BD (exp2 domain), online softmax
            float ml0 = -1e30f, ml1 = -1e30f;
#pragma unroll
            for (int nt = 0; nt < 4; nt++)
#pragma unroll
                for (int e = 0; e < 4; e++) {
                    float sv = fmaf(bd[nt][e], CSC, sacc[nt][e]);
                    sacc[nt][e] = sv;
                    if (e < 2) ml0 = fmaxf(ml0, sv); else ml1 = fmaxf(ml1, sv);
                }
            ml0 = fmaxf(ml0, __shfl_xor_sync(0xFFFFFFFFu, ml0, 1));
            ml0 = fmaxf(ml0, __shfl_xor_sync(0xFFFFFFFFu, ml0, 2));
            ml1 = fmaxf(ml1, __shfl_xor_sync(0xFFFFFFFFu, ml1, 1));
            ml1 = fmaxf(ml1, __shfl_xor_sync(0xFFFFFFFFu, ml1, 2));

            float mn0 = fmaxf(m0, ml0), mn1 = fmaxf(m1, ml1);
            float f0 = ex2f(m0 - mn0), f1 = ex2f(m1 - mn1);
            m0 = mn0; m1 = mn1;

            float ls0 = 0.f, ls1 = 0.f;
#pragma unroll
            for (int nt = 0; nt < 4; nt++) {
                float p0 = ex2f(sacc[nt][0] - m0);
                float p1 = ex2f(sacc[nt][1] - m0);
                float p2 = ex2f(sacc[nt][2] - m1);
                float p3 = ex2f(sacc[nt][3] - m1);
                sacc[nt][0] = p0; sacc[nt][1] = p1; sacc[nt][2] = p2; sacc[nt][3] = p3;
                ls0 += p0 + p1;  ls1 += p2 + p3;
            }
            ls0 += __shfl_xor_sync(0xFFFFFFFFu, ls0, 1);
            ls0 += __shfl_xor_sync(0xFFFFFFFFu, ls0, 2);
            ls1 += __shfl_xor_sync(0xFFFFFFFFu, ls1, 1);
            ls1 += __shfl_xor_sync(0xFFFFFFFFu, ls1, 2);
            l0 = l0 * f0 + ls0;
            l1 = l1 * f1 + ls1;

#pragma unroll
            for (int dt = 0; dt < 8; dt++) {
                pacc[dt][0] *= f0; pacc[dt][1] *= f0;
                pacc[dt][2] *= f1; pacc[dt][3] *= f1;
            }

            // pack P (C-frag pair -> A-frag), fp16
            uint32_t pf[2][4];
#pragma unroll
            for (int ks = 0; ks < 2; ks++) {
                pf[ks][0] = cvt2h(sacc[2*ks][0],   sacc[2*ks][1]);
                pf[ks][1] = cvt2h(sacc[2*ks][2],   sacc[2*ks][3]);
                pf[ks][2] = cvt2h(sacc[2*ks+1][0], sacc[2*ks+1][1]);
                pf[ks][3] = cvt2h(sacc[2*ks+1][2], sacc[2*ks+1][3]);
            }

            // pacc += P @ V
#pragma unroll
            for (int ks = 0; ks < 2; ks++) {
                uint32_t vf[8][2];
#pragma unroll
                for (int dt2 = 0; dt2 < 4; dt2++) {
                    int krow = (sub << 5) + ks*16 + (lane & 7) + ((lane >> 3) & 1)*8;
                    int ncol = dt2*16 + ((lane >> 4) << 3);
                    uint32_t tmp[4];
                    ldm4t(KB + FV*2 + (uint32_t)(krow*FP + ncol)*2, tmp);
                    vf[dt2*2][0]=tmp[0]; vf[dt2*2][1]=tmp[1];
                    vf[dt2*2+1][0]=tmp[2]; vf[dt2*2+1][1]=tmp[3];
                }
#pragma unroll
                for (int dt = 0; dt < 8; dt++)
                    mma_h(pacc[dt], pf[ks], vf[dt]);
            }
        }
    }

    // normalize & write AO (fp16 plane)
    float inv0 = 1.f / l0, inv1 = 1.f / l1;
    const size_t o_r  = (brow + i_r)  * Dn + hoff;
    const size_t o_r8 = (brow + i_r8) * Dn + hoff;
#pragma unroll
    for (int dt = 0; dt < 8; dt++) {
        int d = dt*8 + 2*qq;
        *(uint32_t*)&g_AO[o_r + d]  = cvt2h(pacc[dt][0]*inv0, pacc[dt][1]*inv0);
        *(uint32_t*)&g_AO[o_r8 + d] = cvt2h(pacc[dt][2]*inv1, pacc[dt][3]*inv1);
    }
}

// ---------------------------------------------------------------------------
// Launch
// ---------------------------------------------------------------------------
extern "C" void kernel_launch(void* const* d_in, const int* in_sizes, int n_in,
                              void* d_out, int out_size)
{
    const float* x   = (const float*)d_in[0];
    const float* pos = (const float*)d_in[1];
    const float* Wq  = (const float*)d_in[2];
    const float* bq  = (const float*)d_in[3];
    const float* Wk  = (const float*)d_in[4];
    const float* bk  = (const float*)d_in[5];
    const float* Wv  = (const float*)d_in[6];
    const float* bv  = (const float*)d_in[7];
    const float* Wo  = (const float*)d_in[8];
    const float* bo  = (const float*)d_in[9];
    const float* Wkr = (const float*)d_in[10];
    const float* bkr = (const float*)d_in[11];
    const float* u   = (const float*)d_in[12];
    // d_in[13] (v) unused: GH term is per-row constant -> softmax-invariant.

    uint16_t *px, *pp;
    cudaGetSymbolAddress((void**)&px, g_x);
    cudaGetSymbolAddress((void**)&pp, g_p);

    cudaFuncSetAttribute(proj_fused,  cudaFuncAttributeMaxDynamicSharedMemorySize, GEMM_SMEM);
    cudaFuncSetAttribute(mma_gemm_wo, cudaFuncAttributeMaxDynamicSharedMemorySize, GEMM_SMEM);
    cudaFuncSetAttribute(mma_gemm_t,  cudaFuncAttributeMaxDynamicSharedMemorySize, TSMEM);
    cudaFuncSetAttribute(flash_mma,   cudaFuncAttributeMaxDynamicSharedMemorySize, FLASH_SMEM);
    cudaFuncSetAttribute(flash_mma,   cudaFuncAttributePreferredSharedMemoryCarveout, 100);

    conv_elem<<<(Bn*Sn*Dn/4 + 255)/256, 256>>>(x,   px, Bn*Sn*Dn/4);
    conv_elem<<<(Sn*Dn/4 + 255)/256,    256>>>(pos, pp, Sn*Dn/4);
    conv_wt<<<dim3(Dn/32, Dn/32, 5), 256>>>(Wq, Wk, Wv, Wkr, Wo);

    proj_fused<<<dim3(Dn/128, (Bn*Sn)/128, 4), 256, GEMM_SMEM>>>(bq, bk, bv, bkr);
    mma_gemm_t<<<dim3(Sn/128, Sn/128, BHn), 256, TSMEM>>>();
    flash_mma<<<dim3(Sn/128, BHn), 256, FLASH_SMEM>>>(u);
    mma_gemm_wo<<<dim3(Dn/128, (Bn*Sn)/128), 256, GEMM_SMEM>>>(bo, (float*)d_out);
}

// round 13
// speedup vs baseline: 1.8838x; 1.0905x over previous
#include <cuda_runtime.h>
#include <cuda_fp16.h>
#include <stdint.h>

// Problem constants
#define Bn  2
#define Sn  2048
#define Dn  1024
#define Hn  16
#define DHn 64
#define BHn (Bn*Hn)
#define CSC 0.18033688f   // 0.125 * log2(e)

// ---------------------------------------------------------------------------
// Scratch — single fp16 planes (tensor inputs), fp32 T
// ---------------------------------------------------------------------------
__device__ uint16_t g_Q [(size_t)Bn*Sn*Dn];
__device__ uint16_t g_K [(size_t)Bn*Sn*Dn];
__device__ uint16_t g_V [(size_t)Bn*Sn*Dn];
__device__ uint16_t g_KR[(size_t)Sn*Dn];
__device__ uint16_t g_x [(size_t)Bn*Sn*Dn];
__device__ uint16_t g_p [(size_t)Sn*Dn];
__device__ uint16_t g_Wt[(size_t)5*Dn*Dn];      // q,k,v,kr,o transposed [n][k]
__device__ uint16_t g_AO[(size_t)Bn*Sn*Dn];
__device__ float    g_T [(size_t)BHn*Sn*Sn];

// ---------------------------------------------------------------------------
// Helpers
// ---------------------------------------------------------------------------
__device__ __forceinline__ uint32_t smem_u32(const void* p) {
    uint32_t a;
    asm("{ .reg .u64 t; cvta.to.shared.u64 t, %1; cvt.u32.u64 %0, t; }"
        : "=r"(a) : "l"(p));
    return a;
}
__device__ __forceinline__ void ldm4(uint32_t addr, uint32_t* r) {
    asm volatile("ldmatrix.sync.aligned.m8n8.x4.shared.b16 {%0,%1,%2,%3}, [%4];"
        : "=r"(r[0]), "=r"(r[1]), "=r"(r[2]), "=r"(r[3]) : "r"(addr));
}
__device__ __forceinline__ void ldm4t(uint32_t addr, uint32_t* r) {
    asm volatile("ldmatrix.sync.aligned.m8n8.x4.trans.shared.b16 {%0,%1,%2,%3}, [%4];"
        : "=r"(r[0]), "=r"(r[1]), "=r"(r[2]), "=r"(r[3]) : "r"(addr));
}
__device__ __forceinline__ void mma_h(float* c, const uint32_t* a, const uint32_t* b) {
    asm volatile(
        "mma.sync.aligned.m16n8k16.row.col.f32.f16.f16.f32 "
        "{%0,%1,%2,%3}, {%4,%5,%6,%7}, {%8,%9}, {%0,%1,%2,%3};"
        : "+f"(c[0]), "+f"(c[1]), "+f"(c[2]), "+f"(c[3])
        : "r"(a[0]), "r"(a[1]), "r"(a[2]), "r"(a[3]), "r"(b[0]), "r"(b[1]));
}
__device__ __forceinline__ float ex2f(float x) {
    float y; asm("ex2.approx.ftz.f32 %0, %1;" : "=f"(y) : "f"(x)); return y;
}
__device__ __forceinline__ uint32_t cvt2h(float x0, float x1) {
    uint32_t w;
    asm("cvt.rn.f16x2.f32 %0, %1, %2;" : "=r"(w) : "f"(x1), "f"(x0));
    return w;
}
__device__ __forceinline__ float2 unpack_h2(uint32_t w) {
    __half2 h = *reinterpret_cast<__half2*>(&w);
    return __half22float2(h);
}
__device__ __forceinline__ void cpa16(uint32_t dst, const void* src) {
    asm volatile("cp.async.cg.shared.global [%0], [%1], 16;" :: "r"(dst), "l"(src));
}
#define CPA_COMMIT()  asm volatile("cp.async.commit_group;" ::: "memory")
#define CPA_WAIT(N)   asm volatile("cp.async.wait_group %0;" :: "n"(N) : "memory")

// ---------------------------------------------------------------------------
// One-time fp16 conversion kernels
// ---------------------------------------------------------------------------
__global__ __launch_bounds__(256)
void conv_elem(const float* __restrict__ src, uint16_t* __restrict__ d, int n4)
{
    int i = blockIdx.x * 256 + threadIdx.x;
    if (i >= n4) return;
    float4 v = ((const float4*)src)[i];
    ((uint32_t*)d)[i*2]     = cvt2h(v.x, v.y);
    ((uint32_t*)d)[i*2 + 1] = cvt2h(v.z, v.w);
}

__global__ __launch_bounds__(256)
void conv_wt(const float* __restrict__ Wq, const float* __restrict__ Wk,
             const float* __restrict__ Wv, const float* __restrict__ Wkr,
             const float* __restrict__ Wo)
{
    __shared__ float tile[32][33];
    const int z = blockIdx.z;
    const float* W = (z == 0) ? Wq : (z == 1) ? Wk : (z == 2) ? Wv
                   : (z == 3) ? Wkr : Wo;
    uint16_t* o = g_Wt + (size_t)z * Dn * Dn;
    const int k0 = blockIdx.y << 5, n0 = blockIdx.x << 5;
    const int tr = threadIdx.x >> 5, tc = threadIdx.x & 31;
#pragma unroll
    for (int i = 0; i < 4; i++)
        tile[tr + i*8][tc] = W[(size_t)(k0 + tr + i*8) * Dn + n0 + tc];
    __syncthreads();
#pragma unroll
    for (int i = 0; i < 4; i++) {
        int n = tr + i*8;
        __half hv = __float2half_rn(tile[tc][n]);
        o[(size_t)(n0 + n) * Dn + k0 + tc] = *reinterpret_cast<uint16_t*>(&hv);
    }
}

// ---------------------------------------------------------------------------
// fp16 plane GEMM: 256 thr, 8 warps (32x64), 5-stage cp.async, 2 blocks/SM.
// ---------------------------------------------------------------------------
#define SPITCH 40
#define GOA 0
#define GOB 5120
#define GSTAGE_SZ 10240
#define NSTG 5
#define GEMM_SMEM (NSTG*GSTAGE_SZ*2)

__device__ __forceinline__
void gemm_issue(uint32_t stage_b, const uint16_t* A, const uint16_t* B,
                int k0, int row0, int col0, int t)
{
    const int p = t >> 7, r = t & 127;
    const uint16_t* S = (p ? B + (size_t)(col0 + r) * Dn
                           : A + (size_t)(row0 + r) * Dn) + k0;
    uint32_t d = stage_b + (p ? GOB : GOA)*2 + r*80;
#pragma unroll
    for (int i = 0; i < 4; i++)
        cpa16(d + i*16, S + i*8);
}

template<bool PLANE>
__device__ __forceinline__
void gemm_body(const uint16_t* __restrict__ A, const uint16_t* __restrict__ B,
               const float* __restrict__ bias, float* __restrict__ C,
               uint16_t* __restrict__ Cp,
               int row0, int col0, uint16_t* sm)
{
    const int t = threadIdx.x, lane = t & 31, wid = t >> 5;
    const int m0w = (wid & 3) << 5, n0w = (wid >> 2) << 6;
    const int q = lane >> 3, r8 = lane & 7;
    const uint32_t sb = smem_u32(sm);
    const int NC = Dn >> 5;

#pragma unroll
    for (int s = 0; s < 4; s++) {
        gemm_issue(sb + s*GSTAGE_SZ*2, A, B, s*32, row0, col0, t);
        CPA_COMMIT();
    }

    float acc[2][8][4];
#pragma unroll
    for (int mt = 0; mt < 2; mt++)
#pragma unroll
        for (int nt = 0; nt < 8; nt++)
#pragma unroll
            for (int c = 0; c < 4; c++) acc[mt][nt][c] = 0.f;

    for (int c = 0; c < NC; c++) {
        CPA_WAIT(3);
        __syncthreads();
        if (c + 4 < NC)
            gemm_issue(sb + ((c + 4) % NSTG) * GSTAGE_SZ * 2,
                       A, B, (c + 4) * 32, row0, col0, t);
        CPA_COMMIT();

        const uint32_t cb = sb + (c % NSTG) * GSTAGE_SZ * 2;
#pragma unroll
        for (int ks = 0; ks < 2; ks++) {
            uint32_t af[2][4];
#pragma unroll
            for (int mt = 0; mt < 2; mt++) {
                int row = m0w + mt*16 + r8 + (q & 1)*8;
                int col = ks*16 + (q >> 1)*8;
                ldm4(cb + GOA*2 + (uint32_t)(row*SPITCH + col)*2, af[mt]);
            }
            uint32_t bf[8][2];
#pragma unroll
            for (int bt = 0; bt < 4; bt++) {
                int row = n0w + bt*16 + r8 + (q >> 1)*8;
                int col = ks*16 + (q & 1)*8;
                uint32_t tmp[4];
                ldm4(cb + GOB*2 + (uint32_t)(row*SPITCH + col)*2, tmp);
                bf[bt*2][0]=tmp[0]; bf[bt*2][1]=tmp[1];
                bf[bt*2+1][0]=tmp[2]; bf[bt*2+1][1]=tmp[3];
            }
#pragma unroll
            for (int mt = 0; mt < 2; mt++)
#pragma unroll
                for (int nt = 0; nt < 8; nt++)
                    mma_h(acc[mt][nt], af[mt], bf[nt]);
        }
    }

#pragma unroll
    for (int mt = 0; mt < 2; mt++) {
        int m = row0 + m0w + mt*16 + lane/4;
#pragma unroll
        for (int nt = 0; nt < 8; nt++) {
            int n = col0 + n0w + nt*8 + (lane & 3)*2;
            float2 b2 = *(const float2*)(bias + n);
            float v0 = acc[mt][nt][0] + b2.x, v1 = acc[mt][nt][1] + b2.y;
            float v2 = acc[mt][nt][2] + b2.x, v3 = acc[mt][nt][3] + b2.y;
            if (PLANE) {
                *(uint32_t*)&Cp[(size_t)m*Dn + n]     = cvt2h(v0, v1);
                *(uint32_t*)&Cp[(size_t)(m+8)*Dn + n] = cvt2h(v2, v3);
            } else {
                *(float2*)(C + (size_t)m * Dn + n)       = make_float2(v0, v1);
                *(float2*)(C + (size_t)(m + 8) * Dn + n) = make_float2(v2, v3);
            }
        }
    }
}

__global__ __launch_bounds__(256, 2)
void proj_fused(const float* __restrict__ bq, const float* __restrict__ bk,
                const float* __restrict__ bv, const float* __restrict__ bkr)
{
    extern __shared__ uint16_t gsm[];
    const int z = blockIdx.z;
    const int row0 = blockIdx.y << 7, col0 = blockIdx.x << 7;
    if (z == 3 && row0 >= Sn) return;
    const uint16_t* A = (z < 3) ? g_x : g_p;
    const float* bias; uint16_t* Cp;
    if      (z == 0) { bias = bq;  Cp = g_Q;  }
    else if (z == 1) { bias = bk;  Cp = g_K;  }
    else if (z == 2) { bias = bv;  Cp = g_V;  }
    else             { bias = bkr; Cp = g_KR; }
    gemm_body<true>(A, g_Wt + (size_t)z * Dn * Dn, bias, nullptr, Cp,
                    row0, col0, gsm);
}

__global__ __launch_bounds__(256, 2)
void mma_gemm_wo(const float* __restrict__ bias, float* __restrict__ C)
{
    extern __shared__ uint16_t gsm[];
    gemm_body<false>(g_AO, g_Wt + (size_t)4 * Dn * Dn, bias, C, nullptr,
                     blockIdx.y << 7, blockIdx.x << 7, gsm);
}

// ---------------------------------------------------------------------------
// NT GEMM (fp16):  T[bh] = Q_bh [S,64] @ KR_h^T.  2 blocks/SM, float2 stores.
// ---------------------------------------------------------------------------
#define TP 72
#define TA 0
#define TB (128*TP)
#define TSMEM (2*128*TP*2)

__global__ __launch_bounds__(256, 2)
void mma_gemm_t()
{
    extern __shared__ uint16_t tsm[];
    const int t = threadIdx.x, lane = t & 31, wid = t >> 5;
    const int bh = blockIdx.z, b = bh >> 4, h = bh & 15;
    const int row0 = blockIdx.y << 7, col0 = blockIdx.x << 7;
    const int m0w = (wid & 3) << 5, n0w = (wid >> 2) << 6;
    const int q = lane >> 3, r8 = lane & 7;

    float* C = g_T + (size_t)bh * Sn * Sn;

    {
        const int r = t >> 1, c = (t & 1) << 5;
        const size_t soA = ((size_t)b*Sn + row0 + r) * Dn + h*DHn + c;
        const size_t soB = ((size_t)col0 + r) * Dn + h*DHn + c;
        const uint32_t sb = smem_u32(tsm);
        uint32_t da = sb + (TA + r*TP + c)*2;
        uint32_t db = sb + (TB + r*TP + c)*2;
#pragma unroll
        for (int i = 0; i < 4; i++) {
            cpa16(da + i*16, g_Q  + soA + i*8);
            cpa16(db + i*16, g_KR + soB + i*8);
        }
        CPA_COMMIT();
        CPA_WAIT(0);
    }
    __syncthreads();

    float acc[2][8][4];
#pragma unroll
    for (int mt = 0; mt < 2; mt++)
#pragma unroll
        for (int nt = 0; nt < 8; nt++)
#pragma unroll
            for (int c = 0; c < 4; c++) acc[mt][nt][c] = 0.f;

    const uint32_t cb = smem_u32(tsm);
#pragma unroll
    for (int ks = 0; ks < 4; ks++) {
        uint32_t af[2][4];
#pragma unroll
        for (int mt = 0; mt < 2; mt++) {
            int row = m0w + mt*16 + r8 + (q & 1)*8;
            int col = ks*16 + (q >> 1)*8;
            ldm4(cb + TA*2 + (uint32_t)(row*TP + col)*2, af[mt]);
        }
        uint32_t bf[8][2];
#pragma unroll
        for (int bt = 0; bt < 4; bt++) {
            int row = n0w + bt*16 + r8 + (q >> 1)*8;
            int col = ks*16 + (q & 1)*8;
            uint32_t tmp[4];
            ldm4(cb + TB*2 + (uint32_t)(row*TP + col)*2, tmp);
            bf[bt*2][0]=tmp[0]; bf[bt*2][1]=tmp[1];
            bf[bt*2+1][0]=tmp[2]; bf[bt*2+1][1]=tmp[3];
        }
#pragma unroll
        for (int mt = 0; mt < 2; mt++)
#pragma unroll
            for (int nt = 0; nt < 8; nt++)
                mma_h(acc[mt][nt], af[mt], bf[nt]);
    }

#pragma unroll
    for (int mt = 0; mt < 2; mt++) {
        int m = row0 + m0w + mt*16 + lane/4;
#pragma unroll
        for (int nt = 0; nt < 8; nt++) {
            int n = col0 + n0w + nt*8 + (lane & 3)*2;
            *(float2*)(C + (size_t)m * Sn + n) =
                make_float2(acc[mt][nt][0], acc[mt][nt][1]);
            *(float2*)(C + (size_t)(m + 8) * Sn + n) =
                make_float2(acc[mt][nt][2], acc[mt][nt][3]);
        }
    }
}

// ---------------------------------------------------------------------------
// Flash attention (fp16): 3-stage cp.async ring, ONE softmax per 64-j tile,
// Q-fragments hoisted, exp2 softmax, 2 blocks/SM.
// ---------------------------------------------------------------------------
#define FP 72
#define FQ 0
#define FSTG0 (128*FP)
#define FSTG_SZ (2*64*FP)
#define FK 0
#define FV (64*FP)
#define FNS 3
#define FLASH_SMEM ((128*FP + FNS*2*64*FP) * 2)

__device__ __forceinline__
void flash_issue(uint32_t base, int s, size_t brow, int j0, int hoff, int t)
{
    const int jr = t >> 2, cb = (t & 3) << 4;
    const size_t so = (brow + j0 + jr) * Dn + hoff + cb;
    const uint32_t st = base + (FSTG0 + s*FSTG_SZ + jr*FP + cb) * 2;
    cpa16(st + FK*2,      g_K + so);  cpa16(st + FK*2 + 16, g_K + so + 8);
    cpa16(st + FV*2,      g_V + so);  cpa16(st + FV*2 + 16, g_V + so + 8);
}

__global__ __launch_bounds__(256, 2)
void flash_mma(const float* __restrict__ u)
{
    extern __shared__ uint16_t fsm[];
    const int t = threadIdx.x, lane = t & 31, w = t >> 5;
    const int q = lane >> 3, r8 = lane & 7;
    const int r = lane >> 2, qq = lane & 3;
    const int bh = blockIdx.y, b = bh >> 4, h = bh & 15;
    const int i0 = blockIdx.x << 7;

    const float* Tg = g_T + (size_t)bh*Sn*Sn;
    const uint32_t base = smem_u32(fsm);
    const size_t brow = (size_t)b * Sn;
    const int hoff = h * DHn;

    flash_issue(base, 0, brow, 0,  hoff, t);
    CPA_COMMIT();
    flash_issue(base, 1, brow, 64, hoff, t);
    CPA_COMMIT();

    // stage Q: (q + u)*CSC -> fp16
    {
        const int qr = t >> 1, cb = (t & 1) << 5;
        const size_t so = (brow + i0 + qr) * Dn + hoff + cb;
        float uu[32];
#pragma unroll
        for (int i = 0; i < 32; i += 4)
            *(float4*)(uu + i) = *(const float4*)(u + hoff + cb + i);
#pragma unroll
        for (int i = 0; i < 32; i += 8) {
            uint4 hv = *(const uint4*)(g_Q + so + i);
            uint32_t hw[4] = {hv.x, hv.y, hv.z, hv.w};
#pragma unroll
            for (int k = 0; k < 4; k++) {
                float2 f = unpack_h2(hw[k]);
                *(uint32_t*)&fsm[FQ + qr*FP + cb + i + 2*k] =
                    cvt2h((f.x + uu[i + 2*k]) * CSC, (f.y + uu[i + 2*k + 1]) * CSC);
            }
        }
    }
    __syncthreads();

    // hoisted Q fragments
    uint32_t qf[4][4];
#pragma unroll
    for (int ks = 0; ks < 4; ks++) {
        int row = w*16 + r8 + (q & 1)*8;
        int col = ks*16 + (q >> 1)*8;
        ldm4(base + FQ*2 + (uint32_t)(row*FP + col)*2, qf[ks]);
    }

    float pacc[8][4];
#pragma unroll
    for (int dt = 0; dt < 8; dt++)
#pragma unroll
        for (int c = 0; c < 4; c++) pacc[dt][c] = 0.f;
    float m0 = -1e30f, m1 = -1e30f, l0 = 0.f, l1 = 0.f;

    const int i_r  = i0 + w*16 + r;
    const int i_r8 = i_r + 8;

    for (int j0 = 0; j0 < Sn; j0 += 64) {
        const int ti = j0 >> 6;
        CPA_WAIT(1);
        __syncthreads();
        if (j0 + 128 < Sn) flash_issue(base, (ti + 2) % FNS, brow, j0 + 128, hoff, t);
        CPA_COMMIT();

        const uint32_t KB = base + (FSTG0 + (ti % FNS)*FSTG_SZ) * 2;

        // ---- BD first half prefetch (overlaps S-MMAs)
        float bdA[4][4];
#pragma unroll
        for (int nt = 0; nt < 4; nt++) {
            int jb = j0 + nt*8 + 2*qq;
#pragma unroll
            for (int e = 0; e < 4; e++) {
                int i = (e < 2) ? i_r : i_r8;
                int j = jb + (e & 1);
                int ir = (j <= i) ? i : i + 1;
                int ic = (j <= i) ? (Sn - 1 - i + j) : (j - i - 2);
                float v = __ldg(Tg + (size_t)ir * Sn + ic);
                bdA[nt][e] = (j == i + 1) ? 0.f : v;
            }
        }

        // ---- S = Q @ K^T over the FULL 64-j tile
        float sacc[8][4];
#pragma unroll
        for (int nt = 0; nt < 8; nt++)
#pragma unroll
            for (int c = 0; c < 4; c++) sacc[nt][c] = 0.f;

#pragma unroll
        for (int ks = 0; ks < 4; ks++) {
            uint32_t kf[8][2];
#pragma unroll
            for (int bt = 0; bt < 4; bt++) {
                int row = bt*16 + r8 + (q >> 1)*8;
                int col = ks*16 + (q & 1)*8;
                uint32_t tmp[4];
                ldm4(KB + FK*2 + (uint32_t)(row*FP + col)*2, tmp);
                kf[bt*2][0]=tmp[0]; kf[bt*2][1]=tmp[1];
                kf[bt*2+1][0]=tmp[2]; kf[bt*2+1][1]=tmp[3];
            }
#pragma unroll
            for (int nt = 0; nt < 8; nt++)
                mma_h(sacc[nt], qf[ks], kf[nt]);
        }

        // ---- add BD first half, then load+add second half
#pragma unroll
        for (int nt = 0; nt < 4; nt++)
#pragma unroll
            for (int e = 0; e < 4; e++)
                sacc[nt][e] = fmaf(bdA[nt][e], CSC, sacc[nt][e]);
#pragma unroll
        for (int nt = 0; nt < 4; nt++) {
            int jb = j0 + 32 + nt*8 + 2*qq;
#pragma unroll
            for (int e = 0; e < 4; e++) {
                int i = (e < 2) ? i_r : i_r8;
                int j = jb + (e & 1);
                int ir = (j <= i) ? i : i + 1;
                int ic = (j <= i) ? (Sn - 1 - i + j) : (j - i - 2);
                float v = __ldg(Tg + (size_t)ir * Sn + ic);
                v = (j == i + 1) ? 0.f : v;
                sacc[4 + nt][e] = fmaf(v, CSC, sacc[4 + nt][e]);
            }
        }

        // ---- ONE online-softmax update per 64-j tile
        float ml0 = -1e30f, ml1 = -1e30f;
#pragma unroll
        for (int nt = 0; nt < 8; nt++) {
            ml0 = fmaxf(ml0, fmaxf(sacc[nt][0], sacc[nt][1]));
            ml1 = fmaxf(ml1, fmaxf(sacc[nt][2], sacc[nt][3]));
        }
        ml0 = fmaxf(ml0, __shfl_xor_sync(0xFFFFFFFFu, ml0, 1));
        ml0 = fmaxf(ml0, __shfl_xor_sync(0xFFFFFFFFu, ml0, 2));
        ml1 = fmaxf(ml1, __shfl_xor_sync(0xFFFFFFFFu, ml1, 1));
        ml1 = fmaxf(ml1, __shfl_xor_sync(0xFFFFFFFFu, ml1, 2));

        float mn0 = fmaxf(m0, ml0), mn1 = fmaxf(m1, ml1);
        float f0 = ex2f(m0 - mn0), f1 = ex2f(m1 - mn1);
        m0 = mn0; m1 = mn1;

        float ls0 = 0.f, ls1 = 0.f;
#pragma unroll
        for (int nt = 0; nt < 8; nt++) {
            float p0 = ex2f(sacc[nt][0] - m0);
            float p1 = ex2f(sacc[nt][1] - m0);
            float p2 = ex2f(sacc[nt][2] - m1);
            float p3 = ex2f(sacc[nt][3] - m1);
            sacc[nt][0] = p0; sacc[nt][1] = p1; sacc[nt][2] = p2; sacc[nt][3] = p3;
            ls0 += p0 + p1;  ls1 += p2 + p3;
        }
        ls0 += __shfl_xor_sync(0xFFFFFFFFu, ls0, 1);
        ls0 += __shfl_xor_sync(0xFFFFFFFFu, ls0, 2);
        ls1 += __shfl_xor_sync(0xFFFFFFFFu, ls1, 1);
        ls1 += __shfl_xor_sync(0xFFFFFFFFu, ls1, 2);
        l0 = l0 * f0 + ls0;
        l1 = l1 * f1 + ls1;

#pragma unroll
        for (int dt = 0; dt < 8; dt++) {
            pacc[dt][0] *= f0; pacc[dt][1] *= f0;
            pacc[dt][2] *= f1; pacc[dt][3] *= f1;
        }

        // ---- pack P (C-frag pair -> A-frag), fp16
        uint32_t pf[4][4];
#pragma unroll
        for (int ks = 0; ks < 4; ks++) {
            pf[ks][0] = cvt2h(sacc[2*ks][0],   sacc[2*ks][1]);
            pf[ks][1] = cvt2h(sacc[2*ks][2],   sacc[2*ks][3]);
            pf[ks][2] = cvt2h(sacc[2*ks+1][0], sacc[2*ks+1][1]);
            pf[ks][3] = cvt2h(sacc[2*ks+1][2], sacc[2*ks+1][3]);
        }

        // ---- pacc += P @ V over the full tile
#pragma unroll
        for (int ks = 0; ks < 4; ks++) {
            uint32_t vf[8][2];
#pragma unroll
            for (int dt2 = 0; dt2 < 4; dt2++) {
                int krow = ks*16 + (lane & 7) + ((lane >> 3) & 1)*8;
                int ncol = dt2*16 + ((lane >> 4) << 3);
                uint32_t tmp[4];
                ldm4t(KB + FV*2 + (uint32_t)(krow*FP + ncol)*2, tmp);
                vf[dt2*2][0]=tmp[0]; vf[dt2*2][1]=tmp[1];
                vf[dt2*2+1][0]=tmp[2]; vf[dt2*2+1][1]=tmp[3];
            }
#pragma unroll
            for (int dt = 0; dt < 8; dt++)
                mma_h(pacc[dt], pf[ks], vf[dt]);
        }
    }

    // normalize & write AO (fp16 plane)
    float inv0 = 1.f / l0, inv1 = 1.f / l1;
    const size_t o_r  = (brow + i_r)  * Dn + hoff;
    const size_t o_r8 = (brow + i_r8) * Dn + hoff;
#pragma unroll
    for (int dt = 0; dt < 8; dt++) {
        int d = dt*8 + 2*qq;
        *(uint32_t*)&g_AO[o_r + d]  = cvt2h(pacc[dt][0]*inv0, pacc[dt][1]*inv0);
        *(uint32_t*)&g_AO[o_r8 + d] = cvt2h(pacc[dt][2]*inv1, pacc[dt][3]*inv1);
    }
}

// ---------------------------------------------------------------------------
// Launch
// ---------------------------------------------------------------------------
extern "C" void kernel_launch(void* const* d_in, const int* in_sizes, int n_in,
                              void* d_out, int out_size)
{
    const float* x   = (const float*)d_in[0];
    const float* pos = (const float*)d_in[1];
    const float* Wq  = (const float*)d_in[2];
    const float* bq  = (const float*)d_in[3];
    const float* Wk  = (const float*)d_in[4];
    const float* bk  = (const float*)d_in[5];
    const float* Wv  = (const float*)d_in[6];
    const float* bv  = (const float*)d_in[7];
    const float* Wo  = (const float*)d_in[8];
    const float* bo  = (const float*)d_in[9];
    const float* Wkr = (const float*)d_in[10];
    const float* bkr = (const float*)d_in[11];
    const float* u   = (const float*)d_in[12];
    // d_in[13] (v) unused: GH term is per-row constant -> softmax-invariant.

    uint16_t *px, *pp;
    cudaGetSymbolAddress((void**)&px, g_x);
    cudaGetSymbolAddress((void**)&pp, g_p);

    cudaFuncSetAttribute(proj_fused,  cudaFuncAttributeMaxDynamicSharedMemorySize, GEMM_SMEM);
    cudaFuncSetAttribute(mma_gemm_wo, cudaFuncAttributeMaxDynamicSharedMemorySize, GEMM_SMEM);
    cudaFuncSetAttribute(mma_gemm_t,  cudaFuncAttributeMaxDynamicSharedMemorySize, TSMEM);
    cudaFuncSetAttribute(flash_mma,   cudaFuncAttributeMaxDynamicSharedMemorySize, FLASH_SMEM);
    cudaFuncSetAttribute(flash_mma,   cudaFuncAttributePreferredSharedMemoryCarveout, 100);

    conv_elem<<<(Bn*Sn*Dn/4 + 255)/256, 256>>>(x,   px, Bn*Sn*Dn/4);
    conv_elem<<<(Sn*Dn/4 + 255)/256,    256>>>(pos, pp, Sn*Dn/4);
    conv_wt<<<dim3(Dn/32, Dn/32, 5), 256>>>(Wq, Wk, Wv, Wkr, Wo);

    proj_fused<<<dim3(Dn/128, (Bn*Sn)/128, 4), 256, GEMM_SMEM>>>(bq, bk, bv, bkr);
    mma_gemm_t<<<dim3(Sn/128, Sn/128, BHn), 256, TSMEM>>>();
    flash_mma<<<dim3(Sn/128, BHn), 256, FLASH_SMEM>>>(u);
    mma_gemm_wo<<<dim3(Dn/128, (Bn*Sn)/128), 256, GEMM_SMEM>>>(bo, (float*)d_out);
}

// round 14
// speedup vs baseline: 2.0459x; 1.0861x over previous
#include <cuda_runtime.h>
#include <cuda_fp16.h>
#include <stdint.h>

// Problem constants
#define Bn  2
#define Sn  2048
#define Dn  1024
#define Hn  16
#define DHn 64
#define BHn (Bn*Hn)
#define CSC 0.18033688f   // 0.125 * log2(e)

// ---------------------------------------------------------------------------
// Scratch — all fp16 planes now, including T
// ---------------------------------------------------------------------------
__device__ uint16_t g_Q [(size_t)Bn*Sn*Dn];
__device__ uint16_t g_K [(size_t)Bn*Sn*Dn];
__device__ uint16_t g_V [(size_t)Bn*Sn*Dn];
__device__ uint16_t g_KR[(size_t)Sn*Dn];
__device__ uint16_t g_x [(size_t)Bn*Sn*Dn];
__device__ uint16_t g_p [(size_t)Sn*Dn];
__device__ uint16_t g_Wt[(size_t)5*Dn*Dn];      // q,k,v,kr,o transposed [n][k]
__device__ uint16_t g_AO[(size_t)Bn*Sn*Dn];
__device__ uint16_t g_T [(size_t)BHn*Sn*Sn];    // fp16 T (268 MB)

// ---------------------------------------------------------------------------
// Helpers
// ---------------------------------------------------------------------------
__device__ __forceinline__ uint32_t smem_u32(const void* p) {
    uint32_t a;
    asm("{ .reg .u64 t; cvta.to.shared.u64 t, %1; cvt.u32.u64 %0, t; }"
        : "=r"(a) : "l"(p));
    return a;
}
__device__ __forceinline__ void ldm4(uint32_t addr, uint32_t* r) {
    asm volatile("ldmatrix.sync.aligned.m8n8.x4.shared.b16 {%0,%1,%2,%3}, [%4];"
        : "=r"(r[0]), "=r"(r[1]), "=r"(r[2]), "=r"(r[3]) : "r"(addr));
}
__device__ __forceinline__ void ldm4t(uint32_t addr, uint32_t* r) {
    asm volatile("ldmatrix.sync.aligned.m8n8.x4.trans.shared.b16 {%0,%1,%2,%3}, [%4];"
        : "=r"(r[0]), "=r"(r[1]), "=r"(r[2]), "=r"(r[3]) : "r"(addr));
}
__device__ __forceinline__ void mma_h(float* c, const uint32_t* a, const uint32_t* b) {
    asm volatile(
        "mma.sync.aligned.m16n8k16.row.col.f32.f16.f16.f32 "
        "{%0,%1,%2,%3}, {%4,%5,%6,%7}, {%8,%9}, {%0,%1,%2,%3};"
        : "+f"(c[0]), "+f"(c[1]), "+f"(c[2]), "+f"(c[3])
        : "r"(a[0]), "r"(a[1]), "r"(a[2]), "r"(a[3]), "r"(b[0]), "r"(b[1]));
}
__device__ __forceinline__ float ex2f(float x) {
    float y; asm("ex2.approx.ftz.f32 %0, %1;" : "=f"(y) : "f"(x)); return y;
}
__device__ __forceinline__ uint32_t cvt2h(float x0, float x1) {
    uint32_t w;
    asm("cvt.rn.f16x2.f32 %0, %1, %2;" : "=r"(w) : "f"(x1), "f"(x0));
    return w;
}
__device__ __forceinline__ float2 unpack_h2(uint32_t w) {
    __half2 h = *reinterpret_cast<__half2*>(&w);
    return __half22float2(h);
}
__device__ __forceinline__ void cpa16(uint32_t dst, const void* src) {
    asm volatile("cp.async.cg.shared.global [%0], [%1], 16;" :: "r"(dst), "l"(src));
}
#define CPA_COMMIT()  asm volatile("cp.async.commit_group;" ::: "memory")
#define CPA_WAIT(N)   asm volatile("cp.async.wait_group %0;" :: "n"(N) : "memory")

// ---------------------------------------------------------------------------
// One-time fp16 conversion kernels
// ---------------------------------------------------------------------------
__global__ __launch_bounds__(256)
void conv_elem(const float* __restrict__ src, uint16_t* __restrict__ d, int n4)
{
    int i = blockIdx.x * 256 + threadIdx.x;
    if (i >= n4) return;
    float4 v = ((const float4*)src)[i];
    ((uint32_t*)d)[i*2]     = cvt2h(v.x, v.y);
    ((uint32_t*)d)[i*2 + 1] = cvt2h(v.z, v.w);
}

__global__ __launch_bounds__(256)
void conv_wt(const float* __restrict__ Wq, const float* __restrict__ Wk,
             const float* __restrict__ Wv, const float* __restrict__ Wkr,
             const float* __restrict__ Wo)
{
    __shared__ float tile[32][33];
    const int z = blockIdx.z;
    const float* W = (z == 0) ? Wq : (z == 1) ? Wk : (z == 2) ? Wv
                   : (z == 3) ? Wkr : Wo;
    uint16_t* o = g_Wt + (size_t)z * Dn * Dn;
    const int k0 = blockIdx.y << 5, n0 = blockIdx.x << 5;
    const int tr = threadIdx.x >> 5, tc = threadIdx.x & 31;
#pragma unroll
    for (int i = 0; i < 4; i++)
        tile[tr + i*8][tc] = W[(size_t)(k0 + tr + i*8) * Dn + n0 + tc];
    __syncthreads();
#pragma unroll
    for (int i = 0; i < 4; i++) {
        int n = tr + i*8;
        __half hv = __float2half_rn(tile[tc][n]);
        o[(size_t)(n0 + n) * Dn + k0 + tc] = *reinterpret_cast<uint16_t*>(&hv);
    }
}

// ---------------------------------------------------------------------------
// fp16 plane GEMM: 256 thr, 8 warps (32x64), 5-stage cp.async, 2 blocks/SM.
// ---------------------------------------------------------------------------
#define SPITCH 40
#define GOA 0
#define GOB 5120
#define GSTAGE_SZ 10240
#define NSTG 5
#define GEMM_SMEM (NSTG*GSTAGE_SZ*2)

__device__ __forceinline__
void gemm_issue(uint32_t stage_b, const uint16_t* A, const uint16_t* B,
                int k0, int row0, int col0, int t)
{
    const int p = t >> 7, r = t & 127;
    const uint16_t* S = (p ? B + (size_t)(col0 + r) * Dn
                           : A + (size_t)(row0 + r) * Dn) + k0;
    uint32_t d = stage_b + (p ? GOB : GOA)*2 + r*80;
#pragma unroll
    for (int i = 0; i < 4; i++)
        cpa16(d + i*16, S + i*8);
}

template<bool PLANE>
__device__ __forceinline__
void gemm_body(const uint16_t* __restrict__ A, const uint16_t* __restrict__ B,
               const float* __restrict__ bias, float* __restrict__ C,
               uint16_t* __restrict__ Cp,
               int row0, int col0, uint16_t* sm)
{
    const int t = threadIdx.x, lane = t & 31, wid = t >> 5;
    const int m0w = (wid & 3) << 5, n0w = (wid >> 2) << 6;
    const int q = lane >> 3, r8 = lane & 7;
    const uint32_t sb = smem_u32(sm);
    const int NC = Dn >> 5;

#pragma unroll
    for (int s = 0; s < 4; s++) {
        gemm_issue(sb + s*GSTAGE_SZ*2, A, B, s*32, row0, col0, t);
        CPA_COMMIT();
    }

    float acc[2][8][4];
#pragma unroll
    for (int mt = 0; mt < 2; mt++)
#pragma unroll
        for (int nt = 0; nt < 8; nt++)
#pragma unroll
            for (int c = 0; c < 4; c++) acc[mt][nt][c] = 0.f;

    for (int c = 0; c < NC; c++) {
        CPA_WAIT(3);
        __syncthreads();
        if (c + 4 < NC)
            gemm_issue(sb + ((c + 4) % NSTG) * GSTAGE_SZ * 2,
                       A, B, (c + 4) * 32, row0, col0, t);
        CPA_COMMIT();

        const uint32_t cb = sb + (c % NSTG) * GSTAGE_SZ * 2;
#pragma unroll
        for (int ks = 0; ks < 2; ks++) {
            uint32_t af[2][4];
#pragma unroll
            for (int mt = 0; mt < 2; mt++) {
                int row = m0w + mt*16 + r8 + (q & 1)*8;
                int col = ks*16 + (q >> 1)*8;
                ldm4(cb + GOA*2 + (uint32_t)(row*SPITCH + col)*2, af[mt]);
            }
            uint32_t bf[8][2];
#pragma unroll
            for (int bt = 0; bt < 4; bt++) {
                int row = n0w + bt*16 + r8 + (q >> 1)*8;
                int col = ks*16 + (q & 1)*8;
                uint32_t tmp[4];
                ldm4(cb + GOB*2 + (uint32_t)(row*SPITCH + col)*2, tmp);
                bf[bt*2][0]=tmp[0]; bf[bt*2][1]=tmp[1];
                bf[bt*2+1][0]=tmp[2]; bf[bt*2+1][1]=tmp[3];
            }
#pragma unroll
            for (int mt = 0; mt < 2; mt++)
#pragma unroll
                for (int nt = 0; nt < 8; nt++)
                    mma_h(acc[mt][nt], af[mt], bf[nt]);
        }
    }

#pragma unroll
    for (int mt = 0; mt < 2; mt++) {
        int m = row0 + m0w + mt*16 + lane/4;
#pragma unroll
        for (int nt = 0; nt < 8; nt++) {
            int n = col0 + n0w + nt*8 + (lane & 3)*2;
            float2 b2 = *(const float2*)(bias + n);
            float v0 = acc[mt][nt][0] + b2.x, v1 = acc[mt][nt][1] + b2.y;
            float v2 = acc[mt][nt][2] + b2.x, v3 = acc[mt][nt][3] + b2.y;
            if (PLANE) {
                *(uint32_t*)&Cp[(size_t)m*Dn + n]     = cvt2h(v0, v1);
                *(uint32_t*)&Cp[(size_t)(m+8)*Dn + n] = cvt2h(v2, v3);
            } else {
                *(float2*)(C + (size_t)m * Dn + n)       = make_float2(v0, v1);
                *(float2*)(C + (size_t)(m + 8) * Dn + n) = make_float2(v2, v3);
            }
        }
    }
}

__global__ __launch_bounds__(256, 2)
void proj_fused(const float* __restrict__ bq, const float* __restrict__ bk,
                const float* __restrict__ bv, const float* __restrict__ bkr)
{
    extern __shared__ uint16_t gsm[];
    const int z = blockIdx.z;
    const int row0 = blockIdx.y << 7, col0 = blockIdx.x << 7;
    if (z == 3 && row0 >= Sn) return;
    const uint16_t* A = (z < 3) ? g_x : g_p;
    const float* bias; uint16_t* Cp;
    if      (z == 0) { bias = bq;  Cp = g_Q;  }
    else if (z == 1) { bias = bk;  Cp = g_K;  }
    else if (z == 2) { bias = bv;  Cp = g_V;  }
    else             { bias = bkr; Cp = g_KR; }
    gemm_body<true>(A, g_Wt + (size_t)z * Dn * Dn, bias, nullptr, Cp,
                    row0, col0, gsm);
}

__global__ __launch_bounds__(256, 2)
void mma_gemm_wo(const float* __restrict__ bias, float* __restrict__ C)
{
    extern __shared__ uint16_t gsm[];
    gemm_body<false>(g_AO, g_Wt + (size_t)4 * Dn * Dn, bias, C, nullptr,
                     blockIdx.y << 7, blockIdx.x << 7, gsm);
}

// ---------------------------------------------------------------------------
// NT GEMM (fp16):  T[bh] = Q_bh [S,64] @ KR_h^T.  fp16 T output (paired stores).
// ---------------------------------------------------------------------------
#define TP 72
#define TA 0
#define TB (128*TP)
#define TSMEM (2*128*TP*2)

__global__ __launch_bounds__(256, 2)
void mma_gemm_t()
{
    extern __shared__ uint16_t tsm[];
    const int t = threadIdx.x, lane = t & 31, wid = t >> 5;
    const int bh = blockIdx.z, b = bh >> 4, h = bh & 15;
    const int row0 = blockIdx.y << 7, col0 = blockIdx.x << 7;
    const int m0w = (wid & 3) << 5, n0w = (wid >> 2) << 6;
    const int q = lane >> 3, r8 = lane & 7;

    uint16_t* C = g_T + (size_t)bh * Sn * Sn;

    {
        const int r = t >> 1, c = (t & 1) << 5;
        const size_t soA = ((size_t)b*Sn + row0 + r) * Dn + h*DHn + c;
        const size_t soB = ((size_t)col0 + r) * Dn + h*DHn + c;
        const uint32_t sb = smem_u32(tsm);
        uint32_t da = sb + (TA + r*TP + c)*2;
        uint32_t db = sb + (TB + r*TP + c)*2;
#pragma unroll
        for (int i = 0; i < 4; i++) {
            cpa16(da + i*16, g_Q  + soA + i*8);
            cpa16(db + i*16, g_KR + soB + i*8);
        }
        CPA_COMMIT();
        CPA_WAIT(0);
    }
    __syncthreads();

    float acc[2][8][4];
#pragma unroll
    for (int mt = 0; mt < 2; mt++)
#pragma unroll
        for (int nt = 0; nt < 8; nt++)
#pragma unroll
            for (int c = 0; c < 4; c++) acc[mt][nt][c] = 0.f;

    const uint32_t cb = smem_u32(tsm);
#pragma unroll
    for (int ks = 0; ks < 4; ks++) {
        uint32_t af[2][4];
#pragma unroll
        for (int mt = 0; mt < 2; mt++) {
            int row = m0w + mt*16 + r8 + (q & 1)*8;
            int col = ks*16 + (q >> 1)*8;
            ldm4(cb + TA*2 + (uint32_t)(row*TP + col)*2, af[mt]);
        }
        uint32_t bf[8][2];
#pragma unroll
        for (int bt = 0; bt < 4; bt++) {
            int row = n0w + bt*16 + r8 + (q >> 1)*8;
            int col = ks*16 + (q & 1)*8;
            uint32_t tmp[4];
            ldm4(cb + TB*2 + (uint32_t)(row*TP + col)*2, tmp);
            bf[bt*2][0]=tmp[0]; bf[bt*2][1]=tmp[1];
            bf[bt*2+1][0]=tmp[2]; bf[bt*2+1][1]=tmp[3];
        }
#pragma unroll
        for (int mt = 0; mt < 2; mt++)
#pragma unroll
            for (int nt = 0; nt < 8; nt++)
                mma_h(acc[mt][nt], af[mt], bf[nt]);
    }

#pragma unroll
    for (int mt = 0; mt < 2; mt++) {
        int m = row0 + m0w + mt*16 + lane/4;
#pragma unroll
        for (int nt = 0; nt < 8; nt++) {
            int n = col0 + n0w + nt*8 + (lane & 3)*2;   // even -> uint32-aligned
            *(uint32_t*)&C[(size_t)m * Sn + n] =
                cvt2h(acc[mt][nt][0], acc[mt][nt][1]);
            *(uint32_t*)&C[(size_t)(m + 8) * Sn + n] =
                cvt2h(acc[mt][nt][2], acc[mt][nt][3]);
        }
    }
}

// ---------------------------------------------------------------------------
// Flash attention (fp16): 3-stage cp.async ring, one softmax per 64-j tile,
// fp16 T gather, Q-fragments hoisted, exp2 softmax, 2 blocks/SM.
// ---------------------------------------------------------------------------
#define FP 72
#define FQ 0
#define FSTG0 (128*FP)
#define FSTG_SZ (2*64*FP)
#define FK 0
#define FV (64*FP)
#define FNS 3
#define FLASH_SMEM ((128*FP + FNS*2*64*FP) * 2)

__device__ __forceinline__
void flash_issue(uint32_t base, int s, size_t brow, int j0, int hoff, int t)
{
    const int jr = t >> 2, cb = (t & 3) << 4;
    const size_t so = (brow + j0 + jr) * Dn + hoff + cb;
    const uint32_t st = base + (FSTG0 + s*FSTG_SZ + jr*FP + cb) * 2;
    cpa16(st + FK*2,      g_K + so);  cpa16(st + FK*2 + 16, g_K + so + 8);
    cpa16(st + FV*2,      g_V + so);  cpa16(st + FV*2 + 16, g_V + so + 8);
}

__global__ __launch_bounds__(256, 2)
void flash_mma(const float* __restrict__ u)
{
    extern __shared__ uint16_t fsm[];
    const int t = threadIdx.x, lane = t & 31, w = t >> 5;
    const int q = lane >> 3, r8 = lane & 7;
    const int r = lane >> 2, qq = lane & 3;
    const int bh = blockIdx.y, b = bh >> 4, h = bh & 15;
    const int i0 = blockIdx.x << 7;

    const __half* Tg = (const __half*)(g_T + (size_t)bh*Sn*Sn);
    const uint32_t base = smem_u32(fsm);
    const size_t brow = (size_t)b * Sn;
    const int hoff = h * DHn;

    flash_issue(base, 0, brow, 0,  hoff, t);
    CPA_COMMIT();
    flash_issue(base, 1, brow, 64, hoff, t);
    CPA_COMMIT();

    // stage Q: (q + u)*CSC -> fp16
    {
        const int qr = t >> 1, cb = (t & 1) << 5;
        const size_t so = (brow + i0 + qr) * Dn + hoff + cb;
        float uu[32];
#pragma unroll
        for (int i = 0; i < 32; i += 4)
            *(float4*)(uu + i) = *(const float4*)(u + hoff + cb + i);
#pragma unroll
        for (int i = 0; i < 32; i += 8) {
            uint4 hv = *(const uint4*)(g_Q + so + i);
            uint32_t hw[4] = {hv.x, hv.y, hv.z, hv.w};
#pragma unroll
            for (int k = 0; k < 4; k++) {
                float2 f = unpack_h2(hw[k]);
                *(uint32_t*)&fsm[FQ + qr*FP + cb + i + 2*k] =
                    cvt2h((f.x + uu[i + 2*k]) * CSC, (f.y + uu[i + 2*k + 1]) * CSC);
            }
        }
    }
    __syncthreads();

    // hoisted Q fragments
    uint32_t qf[4][4];
#pragma unroll
    for (int ks = 0; ks < 4; ks++) {
        int row = w*16 + r8 + (q & 1)*8;
        int col = ks*16 + (q >> 1)*8;
        ldm4(base + FQ*2 + (uint32_t)(row*FP + col)*2, qf[ks]);
    }

    float pacc[8][4];
#pragma unroll
    for (int dt = 0; dt < 8; dt++)
#pragma unroll
        for (int c = 0; c < 4; c++) pacc[dt][c] = 0.f;
    float m0 = -1e30f, m1 = -1e30f, l0 = 0.f, l1 = 0.f;

    const int i_r  = i0 + w*16 + r;
    const int i_r8 = i_r + 8;

    for (int j0 = 0; j0 < Sn; j0 += 64) {
        const int ti = j0 >> 6;
        CPA_WAIT(1);
        __syncthreads();
        if (j0 + 128 < Sn) flash_issue(base, (ti + 2) % FNS, brow, j0 + 128, hoff, t);
        CPA_COMMIT();

        const uint32_t KB = base + (FSTG0 + (ti % FNS)*FSTG_SZ) * 2;

        // ---- BD first half prefetch (fp16, overlaps S-MMAs)
        float bdA[4][4];
#pragma unroll
        for (int nt = 0; nt < 4; nt++) {
            int jb = j0 + nt*8 + 2*qq;
#pragma unroll
            for (int e = 0; e < 4; e++) {
                int i = (e < 2) ? i_r : i_r8;
                int j = jb + (e & 1);
                int ir = (j <= i) ? i : i + 1;
                int ic = (j <= i) ? (Sn - 1 - i + j) : (j - i - 2);
                float v = __half2float(__ldg(Tg + (size_t)ir * Sn + ic));
                bdA[nt][e] = (j == i + 1) ? 0.f : v;
            }
        }

        // ---- S = Q @ K^T over the FULL 64-j tile
        float sacc[8][4];
#pragma unroll
        for (int nt = 0; nt < 8; nt++)
#pragma unroll
            for (int c = 0; c < 4; c++) sacc[nt][c] = 0.f;

#pragma unroll
        for (int ks = 0; ks < 4; ks++) {
            uint32_t kf[8][2];
#pragma unroll
            for (int bt = 0; bt < 4; bt++) {
                int row = bt*16 + r8 + (q >> 1)*8;
                int col = ks*16 + (q & 1)*8;
                uint32_t tmp[4];
                ldm4(KB + FK*2 + (uint32_t)(row*FP + col)*2, tmp);
                kf[bt*2][0]=tmp[0]; kf[bt*2][1]=tmp[1];
                kf[bt*2+1][0]=tmp[2]; kf[bt*2+1][1]=tmp[3];
            }
#pragma unroll
            for (int nt = 0; nt < 8; nt++)
                mma_h(sacc[nt], qf[ks], kf[nt]);
        }

        // ---- add BD first half, then load+add second half
#pragma unroll
        for (int nt = 0; nt < 4; nt++)
#pragma unroll
            for (int e = 0; e < 4; e++)
                sacc[nt][e] = fmaf(bdA[nt][e], CSC, sacc[nt][e]);
#pragma unroll
        for (int nt = 0; nt < 4; nt++) {
            int jb = j0 + 32 + nt*8 + 2*qq;
#pragma unroll
            for (int e = 0; e < 4; e++) {
                int i = (e < 2) ? i_r : i_r8;
                int j = jb + (e & 1);
                int ir = (j <= i) ? i : i + 1;
                int ic = (j <= i) ? (Sn - 1 - i + j) : (j - i - 2);
                float v = __half2float(__ldg(Tg + (size_t)ir * Sn + ic));
                v = (j == i + 1) ? 0.f : v;
                sacc[4 + nt][e] = fmaf(v, CSC, sacc[4 + nt][e]);
            }
        }

        // ---- ONE online-softmax update per 64-j tile
        float ml0 = -1e30f, ml1 = -1e30f;
#pragma unroll
        for (int nt = 0; nt < 8; nt++) {
            ml0 = fmaxf(ml0, fmaxf(sacc[nt][0], sacc[nt][1]));
            ml1 = fmaxf(ml1, fmaxf(sacc[nt][2], sacc[nt][3]));
        }
        ml0 = fmaxf(ml0, __shfl_xor_sync(0xFFFFFFFFu, ml0, 1));
        ml0 = fmaxf(ml0, __shfl_xor_sync(0xFFFFFFFFu, ml0, 2));
        ml1 = fmaxf(ml1, __shfl_xor_sync(0xFFFFFFFFu, ml1, 1));
        ml1 = fmaxf(ml1, __shfl_xor_sync(0xFFFFFFFFu, ml1, 2));

        float mn0 = fmaxf(m0, ml0), mn1 = fmaxf(m1, ml1);
        float f0 = ex2f(m0 - mn0), f1 = ex2f(m1 - mn1);
        m0 = mn0; m1 = mn1;

        float ls0 = 0.f, ls1 = 0.f;
#pragma unroll
        for (int nt = 0; nt < 8; nt++) {
            float p0 = ex2f(sacc[nt][0] - m0);
            float p1 = ex2f(sacc[nt][1] - m0);
            float p2 = ex2f(sacc[nt][2] - m1);
            float p3 = ex2f(sacc[nt][3] - m1);
            sacc[nt][0] = p0; sacc[nt][1] = p1; sacc[nt][2] = p2; sacc[nt][3] = p3;
            ls0 += p0 + p1;  ls1 += p2 + p3;
        }
        ls0 += __shfl_xor_sync(0xFFFFFFFFu, ls0, 1);
        ls0 += __shfl_xor_sync(0xFFFFFFFFu, ls0, 2);
        ls1 += __shfl_xor_sync(0xFFFFFFFFu, ls1, 1);
        ls1 += __shfl_xor_sync(0xFFFFFFFFu, ls1, 2);
        l0 = l0 * f0 + ls0;
        l1 = l1 * f1 + ls1;

#pragma unroll
        for (int dt = 0; dt < 8; dt++) {
            pacc[dt][0] *= f0; pacc[dt][1] *= f0;
            pacc[dt][2] *= f1; pacc[dt][3] *= f1;
        }

        // ---- pack P (C-frag pair -> A-frag), fp16
        uint32_t pf[4][4];
#pragma unroll
        for (int ks = 0; ks < 4; ks++) {
            pf[ks][0] = cvt2h(sacc[2*ks][0],   sacc[2*ks][1]);
            pf[ks][1] = cvt2h(sacc[2*ks][2],   sacc[2*ks][3]);
            pf[ks][2] = cvt2h(sacc[2*ks+1][0], sacc[2*ks+1][1]);
            pf[ks][3] = cvt2h(sacc[2*ks+1][2], sacc[2*ks+1][3]);
        }

        // ---- pacc += P @ V over the full tile
#pragma unroll
        for (int ks = 0; ks < 4; ks++) {
            uint32_t vf[8][2];
#pragma unroll
            for (int dt2 = 0; dt2 < 4; dt2++) {
                int krow = ks*16 + (lane & 7) + ((lane >> 3) & 1)*8;
                int ncol = dt2*16 + ((lane >> 4) << 3);
                uint32_t tmp[4];
                ldm4t(KB + FV*2 + (uint32_t)(krow*FP + ncol)*2, tmp);
                vf[dt2*2][0]=tmp[0]; vf[dt2*2][1]=tmp[1];
                vf[dt2*2+1][0]=tmp[2]; vf[dt2*2+1][1]=tmp[3];
            }
#pragma unroll
            for (int dt = 0; dt < 8; dt++)
                mma_h(pacc[dt], pf[ks], vf[dt]);
        }
    }

    // normalize & write AO (fp16 plane)
    float inv0 = 1.f / l0, inv1 = 1.f / l1;
    const size_t o_r  = (brow + i_r)  * Dn + hoff;
    const size_t o_r8 = (brow + i_r8) * Dn + hoff;
#pragma unroll
    for (int dt = 0; dt < 8; dt++) {
        int d = dt*8 + 2*qq;
        *(uint32_t*)&g_AO[o_r + d]  = cvt2h(pacc[dt][0]*inv0, pacc[dt][1]*inv0);
        *(uint32_t*)&g_AO[o_r8 + d] = cvt2h(pacc[dt][2]*inv1, pacc[dt][3]*inv1);
    }
}

// ---------------------------------------------------------------------------
// Launch
// ---------------------------------------------------------------------------
extern "C" void kernel_launch(void* const* d_in, const int* in_sizes, int n_in,
                              void* d_out, int out_size)
{
    const float* x   = (const float*)d_in[0];
    const float* pos = (const float*)d_in[1];
    const float* Wq  = (const float*)d_in[2];
    const float* bq  = (const float*)d_in[3];
    const float* Wk  = (const float*)d_in[4];
    const float* bk  = (const float*)d_in[5];
    const float* Wv  = (const float*)d_in[6];
    const float* bv  = (const float*)d_in[7];
    const float* Wo  = (const float*)d_in[8];
    const float* bo  = (const float*)d_in[9];
    const float* Wkr = (const float*)d_in[10];
    const float* bkr = (const float*)d_in[11];
    const float* u   = (const float*)d_in[12];
    // d_in[13] (v) unused: GH term is per-row constant -> softmax-invariant.

    uint16_t *px, *pp;
    cudaGetSymbolAddress((void**)&px, g_x);
    cudaGetSymbolAddress((void**)&pp, g_p);

    cudaFuncSetAttribute(proj_fused,  cudaFuncAttributeMaxDynamicSharedMemorySize, GEMM_SMEM);
    cudaFuncSetAttribute(mma_gemm_wo, cudaFuncAttributeMaxDynamicSharedMemorySize, GEMM_SMEM);
    cudaFuncSetAttribute(mma_gemm_t,  cudaFuncAttributeMaxDynamicSharedMemorySize, TSMEM);
    cudaFuncSetAttribute(flash_mma,   cudaFuncAttributeMaxDynamicSharedMemorySize, FLASH_SMEM);
    cudaFuncSetAttribute(flash_mma,   cudaFuncAttributePreferredSharedMemoryCarveout, 100);

    conv_elem<<<(Bn*Sn*Dn/4 + 255)/256, 256>>>(x,   px, Bn*Sn*Dn/4);
    conv_elem<<<(Sn*Dn/4 + 255)/256,    256>>>(pos, pp, Sn*Dn/4);
    conv_wt<<<dim3(Dn/32, Dn/32, 5), 256>>>(Wq, Wk, Wv, Wkr, Wo);

    proj_fused<<<dim3(Dn/128, (Bn*Sn)/128, 4), 256, GEMM_SMEM>>>(bq, bk, bv, bkr);
    mma_gemm_t<<<dim3(Sn/128, Sn/128, BHn), 256, TSMEM>>>();
    flash_mma<<<dim3(Sn/128, BHn), 256, FLASH_SMEM>>>(u);
    mma_gemm_wo<<<dim3(Dn/128, (Bn*Sn)/128), 256, GEMM_SMEM>>>(bo, (float*)d_out);
}